// round 3
// baseline (speedup 1.0000x reference)
#include <cuda_runtime.h>
#include <cuda_bf16.h>
#include <math.h>

// ---------------- problem constants ----------------
#define LAYERS 12
#define DMODEL 768
#define NHEAD  12
#define HD     64
#define TMAXS  1024
#define BATCH  2
#define MROWS  (BATCH*TMAXS)   // 2048
#define VOCAB  50257

// ---------------- scratch ----------------
__device__ float g_x  [MROWS*DMODEL];
__device__ float g_h  [MROWS*DMODEL];
__device__ float g_qkv[MROWS*3*DMODEL];
__device__ float g_y  [MROWS*DMODEL];
__device__ float g_fc [MROWS*4*DMODEL];

// ---------------- helpers ----------------
__device__ __forceinline__ float warp_max(float v){
    #pragma unroll
    for(int o=16;o;o>>=1) v = fmaxf(v, __shfl_xor_sync(0xffffffffu, v, o));
    return v;
}
__device__ __forceinline__ float warp_sum(float v){
    #pragma unroll
    for(int o=16;o;o>>=1) v += __shfl_xor_sync(0xffffffffu, v, o);
    return v;
}
__device__ __forceinline__ float gelu_exact(float v){
    return 0.5f * v * (1.0f + erff(v * 0.70710678118654752440f));
}
__device__ __forceinline__ unsigned f2tf32(float v){
    unsigned u;
    asm("cvt.rna.tf32.f32 %0, %1;" : "=r"(u) : "f"(v));
    return u;
}
__device__ __forceinline__ void ldsm4(unsigned r[4], unsigned addr){
    asm volatile("ldmatrix.sync.aligned.m8n8.x4.shared.b16 {%0,%1,%2,%3}, [%4];"
                 : "=r"(r[0]),"=r"(r[1]),"=r"(r[2]),"=r"(r[3]) : "r"(addr));
}
__device__ __forceinline__ void ldsm2(unsigned r[2], unsigned addr){
    asm volatile("ldmatrix.sync.aligned.m8n8.x2.shared.b16 {%0,%1}, [%2];"
                 : "=r"(r[0]),"=r"(r[1]) : "r"(addr));
}
__device__ __forceinline__ void mma_tf32(float c[4], const unsigned a[4], const unsigned b[2]){
    asm volatile(
        "mma.sync.aligned.m16n8k8.row.col.f32.tf32.tf32.f32 "
        "{%0,%1,%2,%3}, {%4,%5,%6,%7}, {%8,%9}, {%0,%1,%2,%3};\n"
        : "+f"(c[0]), "+f"(c[1]), "+f"(c[2]), "+f"(c[3])
        : "r"(a[0]), "r"(a[1]), "r"(a[2]), "r"(a[3]), "r"(b[0]), "r"(b[1]));
}

// ---------------- embedding ----------------
__global__ void embed_kernel(const int* __restrict__ ids,
                             const float* __restrict__ wte,
                             const float* __restrict__ wpe,
                             float* __restrict__ x)
{
    int i = blockIdx.x * blockDim.x + threadIdx.x;
    if (i >= MROWS*DMODEL) return;
    int row = i / DMODEL;
    int d   = i - row*DMODEL;
    int t   = row & (TMAXS-1);
    int id  = ids[row];
    x[i] = wte[(size_t)id*DMODEL + d] + wpe[(size_t)t*DMODEL + d];
}

// ---------------- layernorm ----------------
__global__ void layernorm_kernel(const float* __restrict__ in,
                                 float* __restrict__ out,
                                 const float* __restrict__ g,
                                 const float* __restrict__ b)
{
    int row = blockIdx.x;
    const float* x = in + (size_t)row*DMODEL;
    float s = 0.f, ss = 0.f;
    for (int i = threadIdx.x; i < DMODEL; i += 256){
        float v = x[i]; s += v; ss += v*v;
    }
    __shared__ float sbuf[8], sbuf2[8];
    s  = warp_sum(s);
    ss = warp_sum(ss);
    if ((threadIdx.x & 31) == 0){ sbuf[threadIdx.x>>5] = s; sbuf2[threadIdx.x>>5] = ss; }
    __syncthreads();
    if (threadIdx.x == 0){
        float S=0.f, SS=0.f;
        #pragma unroll
        for (int i=0;i<8;i++){ S += sbuf[i]; SS += sbuf2[i]; }
        sbuf[0]  = S * (1.0f/DMODEL);
        sbuf2[0] = SS * (1.0f/DMODEL);
    }
    __syncthreads();
    float mean = sbuf[0];
    float var  = sbuf2[0] - mean*mean;
    float rstd = rsqrtf(var + 1e-5f);
    float* o = out + (size_t)row*DMODEL;
    for (int i = threadIdx.x; i < DMODEL; i += 256)
        o[i] = (x[i]-mean)*rstd*g[i] + b[i];
}

// =====================================================================
// TF32 tensor-core GEMM, pre-converted SMEM + ldmatrix mainloop.
//   BT=false: C = A[M,K] @ B[K,N]      (row-major B; M,N mult of 128)
//   BT=true : C = A[M,K] @ Bt[N,K]^T   (lm head; ragged N)
// Block 128x128x32, 256 thr, 8 warps (2x4), warp tile 64x32.
// SMEM holds tf32-converted bits. One __syncthreads per k-tile.
// =====================================================================
#define AS_STRIDE 36
#define BS_NN_STRIDE 136
#define AS_BUF (128*AS_STRIDE)
#define BS_NN_BUF (32*BS_NN_STRIDE)
#define BS_NT_BUF (128*AS_STRIDE)
#define SMEM_NN ((2*AS_BUF + 2*BS_NN_BUF)*4)
#define SMEM_NT ((2*AS_BUF + 2*BS_NT_BUF)*4)

template<int EPI, bool BT>
__global__ __launch_bounds__(256) void mma_gemm(
    const float* __restrict__ A, const float* __restrict__ B,
    const float* __restrict__ bias, const float* __restrict__ resid,
    float* __restrict__ C, int M, int N, int K)
{
    extern __shared__ float smem[];
    float* As = smem;                   // [2][128][36] tf32 bits
    float* Bs = smem + 2*AS_BUF;        // NN: [2][32][136]  NT: [2][128][36]

    const int tid  = threadIdx.x;
    const int lane = tid & 31;
    const int warp = tid >> 5;
    const int wm   = warp >> 2;
    const int wn   = warp & 3;
    const int bm   = blockIdx.y * 128;
    const int bn   = blockIdx.x * 128;
    const int T    = K / 32;
    const unsigned sb = (unsigned)__cvta_generic_to_shared(smem);

    float4 ra[4], rb[4];

    auto ldg = [&](int t){
        const int k0 = t*32;
        #pragma unroll
        for (int p=0;p<4;p++){
            int row=(tid>>3)+p*32, c4=(tid&7)*4;
            ra[p] = *(const float4*)(A + (size_t)(bm+row)*K + k0 + c4);
        }
        if (!BT){
            #pragma unroll
            for (int p=0;p<4;p++){
                int kr=(tid>>5)+p*8, cq=(tid&31)*4;
                rb[p] = *(const float4*)(B + (size_t)(k0+kr)*N + bn + cq);
            }
        } else {
            #pragma unroll
            for (int p=0;p<4;p++){
                int n=(tid>>3)+p*32, kq=(tid&7)*4;
                const float* src = (bn+n < N) ? (B + (size_t)(bn+n)*K + k0 + kq) : B;
                rb[p] = *(const float4*)src;
            }
        }
    };
    auto sts = [&](int buf){
        #pragma unroll
        for (int p=0;p<4;p++){
            int row=(tid>>3)+p*32, c4=(tid&7)*4;
            uint4 v = make_uint4(f2tf32(ra[p].x), f2tf32(ra[p].y),
                                 f2tf32(ra[p].z), f2tf32(ra[p].w));
            *(uint4*)(As + buf*AS_BUF + row*AS_STRIDE + c4) = v;
        }
        if (!BT){
            #pragma unroll
            for (int p=0;p<4;p++){
                int kr=(tid>>5)+p*8, cq=(tid&31)*4;
                uint4 v = make_uint4(f2tf32(rb[p].x), f2tf32(rb[p].y),
                                     f2tf32(rb[p].z), f2tf32(rb[p].w));
                *(uint4*)(Bs + buf*BS_NN_BUF + kr*BS_NN_STRIDE + cq) = v;
            }
        } else {
            #pragma unroll
            for (int p=0;p<4;p++){
                int n=(tid>>3)+p*32, kq=(tid&7)*4;
                uint4 v = make_uint4(f2tf32(rb[p].x), f2tf32(rb[p].y),
                                     f2tf32(rb[p].z), f2tf32(rb[p].w));
                *(uint4*)(Bs + buf*BS_NT_BUF + n*AS_STRIDE + kq) = v;
            }
        }
    };

    float acc[4][4][4];
    #pragma unroll
    for (int i=0;i<4;i++)
        #pragma unroll
        for (int j=0;j<4;j++)
            #pragma unroll
            for (int r=0;r<4;r++) acc[i][j][r]=0.f;

    ldg(0);

    for (int t = 0; t < T; t++){
        const int buf = t & 1;
        sts(buf);
        if (t + 1 < T) ldg(t+1);
        __syncthreads();

        // per-lane ldmatrix row addresses (bytes)
        const unsigned a_addr = sb
            + (unsigned)(buf*AS_BUF + (wm*64 + (lane&15))*AS_STRIDE + ((lane>>4)<<2))*4u;
        const float* Bb = Bs + buf*BS_NN_BUF;   // NN path
        const unsigned b_addr = sb + (unsigned)(2*AS_BUF)*4u
            + (unsigned)(buf*BS_NT_BUF + (lane&7)*AS_STRIDE + (((lane>>3)&1)<<2))*4u; // NT path

        #pragma unroll
        for (int ks = 0; ks < 4; ks++){
            const int kk = ks*8;
            unsigned af[4][4];
            #pragma unroll
            for (int mt = 0; mt < 4; mt++)
                ldsm4(af[mt], a_addr + (unsigned)(mt*16*AS_STRIDE + kk)*4u);
            unsigned bf[4][2];
            if (!BT){
                #pragma unroll
                for (int nt = 0; nt < 4; nt++){
                    int n = wn*32 + nt*8 + (lane>>2);
                    bf[nt][0] = __float_as_uint(Bb[(kk   + (lane&3))*BS_NN_STRIDE + n]);
                    bf[nt][1] = __float_as_uint(Bb[(kk+4 + (lane&3))*BS_NN_STRIDE + n]);
                }
            } else {
                #pragma unroll
                for (int nt = 0; nt < 4; nt++)
                    ldsm2(bf[nt], b_addr + (unsigned)((wn*32 + nt*8)*AS_STRIDE + kk)*4u);
            }
            #pragma unroll
            for (int mt = 0; mt < 4; mt++)
                #pragma unroll
                for (int nt = 0; nt < 4; nt++)
                    mma_tf32(acc[mt][nt], af[mt], bf[nt]);
        }
        // NOTE: no trailing sync needed; top-of-loop barrier protects buffers.
        __syncthreads();
    }

    // epilogue
    #pragma unroll
    for (int mt = 0; mt < 4; mt++){
        #pragma unroll
        for (int nt = 0; nt < 4; nt++){
            int col  = bn + wn*32 + nt*8 + 2*(lane&3);
            int row0 = bm + wm*64 + mt*16 + (lane>>2);
            float b0 = 0.f, b1 = 0.f;
            if (EPI >= 1){
                if (!BT || col   < N) b0 = bias[col];
                if (!BT || col+1 < N) b1 = bias[col+1];
            }
            #pragma unroll
            for (int half = 0; half < 2; half++){
                int row = row0 + half*8;
                float v0 = acc[mt][nt][half*2+0] + b0;
                float v1 = acc[mt][nt][half*2+1] + b1;
                if (EPI == 2){
                    v0 += resid[(size_t)row*N + col];
                    v1 += resid[(size_t)row*N + col + 1];
                }
                if (EPI == 3){ v0 = gelu_exact(v0); v1 = gelu_exact(v1); }
                if (!BT){
                    *(float2*)(C + (size_t)row*N + col) = make_float2(v0, v1);
                } else {
                    if (col   < N) C[(size_t)row*N + col]     = v0;
                    if (col+1 < N) C[(size_t)row*N + col + 1] = v1;
                }
            }
        }
    }
}

// ---------------- attention ----------------
__global__ __launch_bounds__(128) void attention_kernel(
    const float* __restrict__ qkv, float* __restrict__ y)
{
    const int tq = blockIdx.x;
    const int h  = blockIdx.y;
    const int b  = blockIdx.z;
    const int tid = threadIdx.x;

    __shared__ float sq[HD];
    __shared__ float sp[TMAXS];
    __shared__ float rmax[4], rsum[4];
    __shared__ float yc[HD];

    const size_t rowbase = (size_t)(b*TMAXS + tq) * (3*DMODEL);
    if (tid < HD) sq[tid] = qkv[rowbase + h*HD + tid];
    __syncthreads();

    const int nk = tq + 1;

    float lmax = -INFINITY;
    for (int k = tid; k < nk; k += 128){
        const float* kr = qkv + (size_t)(b*TMAXS + k)*(3*DMODEL) + DMODEL + h*HD;
        float dot = 0.f;
        #pragma unroll
        for (int d = 0; d < HD; d += 4){
            float4 kv = *(const float4*)(kr + d);
            dot += sq[d]*kv.x + sq[d+1]*kv.y + sq[d+2]*kv.z + sq[d+3]*kv.w;
        }
        dot *= 0.125f;
        sp[k] = dot;
        lmax = fmaxf(lmax, dot);
    }
    float wm = warp_max(lmax);
    if ((tid & 31) == 0) rmax[tid>>5] = wm;
    __syncthreads();
    float gmax = fmaxf(fmaxf(rmax[0],rmax[1]), fmaxf(rmax[2],rmax[3]));

    float lsum = 0.f;
    for (int k = tid; k < nk; k += 128){
        float e = __expf(sp[k] - gmax);
        sp[k] = e;
        lsum += e;
    }
    float ws = warp_sum(lsum);
    if ((tid & 31) == 0) rsum[tid>>5] = ws;
    __syncthreads();
    float inv = 1.0f / (rsum[0]+rsum[1]+rsum[2]+rsum[3]);

    const int d    = tid & 63;
    const int half = tid >> 6;
    float acc = 0.f;
    for (int k = half; k < nk; k += 2){
        acc += sp[k] * qkv[(size_t)(b*TMAXS + k)*(3*DMODEL) + 2*DMODEL + h*HD + d];
    }
    if (half) yc[d] = acc;
    __syncthreads();
    if (!half)
        y[(size_t)(b*TMAXS + tq)*DMODEL + h*HD + d] = (acc + yc[d]) * inv;
}

// ---------------- host orchestration ----------------
extern "C" void kernel_launch(void* const* d_in, const int* in_sizes, int n_in,
                              void* d_out, int out_size)
{
    const int*   ids    = (const int*)  d_in[0];
    const float* wte    = (const float*)d_in[1];
    const float* wpe    = (const float*)d_in[2];
    const float* ln1_g  = (const float*)d_in[3];
    const float* ln1_b  = (const float*)d_in[4];
    const float* attn_w = (const float*)d_in[5];
    const float* attn_b = (const float*)d_in[6];
    const float* proj_w = (const float*)d_in[7];
    const float* proj_b = (const float*)d_in[8];
    const float* ln2_g  = (const float*)d_in[9];
    const float* ln2_b  = (const float*)d_in[10];
    const float* fc_w   = (const float*)d_in[11];
    const float* fc_b   = (const float*)d_in[12];
    const float* fc2_w  = (const float*)d_in[13];
    const float* fc2_b  = (const float*)d_in[14];
    const float* lnf_g  = (const float*)d_in[15];
    const float* lnf_b  = (const float*)d_in[16];
    float* out = (float*)d_out;

    float *x, *h, *qkv, *y, *fc;
    cudaGetSymbolAddress((void**)&x,   g_x);
    cudaGetSymbolAddress((void**)&h,   g_h);
    cudaGetSymbolAddress((void**)&qkv, g_qkv);
    cudaGetSymbolAddress((void**)&y,   g_y);
    cudaGetSymbolAddress((void**)&fc,  g_fc);

    cudaFuncSetAttribute(mma_gemm<1,false>, cudaFuncAttributeMaxDynamicSharedMemorySize, SMEM_NN);
    cudaFuncSetAttribute(mma_gemm<2,false>, cudaFuncAttributeMaxDynamicSharedMemorySize, SMEM_NN);
    cudaFuncSetAttribute(mma_gemm<3,false>, cudaFuncAttributeMaxDynamicSharedMemorySize, SMEM_NN);
    cudaFuncSetAttribute(mma_gemm<0,true >, cudaFuncAttributeMaxDynamicSharedMemorySize, SMEM_NT);

    embed_kernel<<<(MROWS*DMODEL + 255)/256, 256>>>(ids, wte, wpe, x);

    for (int l = 0; l < LAYERS; l++){
        layernorm_kernel<<<MROWS, 256>>>(x, h, ln1_g + l*DMODEL, ln1_b + l*DMODEL);

        mma_gemm<1,false><<<dim3(3*DMODEL/128, MROWS/128), 256, SMEM_NN>>>(
            h, attn_w + (size_t)l*DMODEL*3*DMODEL, attn_b + (size_t)l*3*DMODEL,
            nullptr, qkv, MROWS, 3*DMODEL, DMODEL);

        attention_kernel<<<dim3(TMAXS, NHEAD, BATCH), 128>>>(qkv, y);

        mma_gemm<2,false><<<dim3(DMODEL/128, MROWS/128), 256, SMEM_NN>>>(
            y, proj_w + (size_t)l*DMODEL*DMODEL, proj_b + (size_t)l*DMODEL,
            x, x, MROWS, DMODEL, DMODEL);

        layernorm_kernel<<<MROWS, 256>>>(x, h, ln2_g + l*DMODEL, ln2_b + l*DMODEL);

        mma_gemm<3,false><<<dim3(4*DMODEL/128, MROWS/128), 256, SMEM_NN>>>(
            h, fc_w + (size_t)l*DMODEL*4*DMODEL, fc_b + (size_t)l*4*DMODEL,
            nullptr, fc, MROWS, 4*DMODEL, DMODEL);

        mma_gemm<2,false><<<dim3(DMODEL/128, MROWS/128), 256, SMEM_NN>>>(
            fc, fc2_w + (size_t)l*4*DMODEL*DMODEL, fc2_b + (size_t)l*DMODEL,
            x, x, MROWS, DMODEL, 4*DMODEL);
    }

    layernorm_kernel<<<MROWS, 256>>>(x, h, lnf_g, lnf_b);

    mma_gemm<0,true><<<dim3((VOCAB + 127)/128, MROWS/128), 256, SMEM_NT>>>(
        h, wte, nullptr, nullptr, out, MROWS, VOCAB, DMODEL);
}

// round 7
// speedup vs baseline: 1.1640x; 1.1640x over previous
#include <cuda_runtime.h>
#include <cuda_fp16.h>
#include <math.h>
#include <cstdint>

// ---------------- problem constants ----------------
#define LAYERS 12
#define DMODEL 768
#define NHEAD  12
#define HD     64
#define TMAXS  1024
#define BATCH  2
#define MROWS  (BATCH*TMAXS)   // 2048
#define VOCAB  50257

// ---------------- scratch (static device memory; no allocation) ----------------
__device__ float  g_x  [MROWS*DMODEL];            // residual stream (fp32)
__device__ float  g_qkv[MROWS*3*DMODEL];          // qkv (fp32, for attention)
__device__ __half g_h16 [MROWS*DMODEL];           // LN outputs (fp16)
__device__ __half g_y16 [MROWS*DMODEL];           // attention out (fp16)
__device__ __half g_fc16[MROWS*4*DMODEL];         // gelu(fc) out (fp16)
__device__ __half g_wqkv16 [LAYERS*3*DMODEL*DMODEL];   // [l][3D][D]
__device__ __half g_wproj16[LAYERS*DMODEL*DMODEL];     // [l][D][D]
__device__ __half g_wfc16  [LAYERS*4*DMODEL*DMODEL];   // [l][4D][D]
__device__ __half g_wfc216 [LAYERS*DMODEL*4*DMODEL];   // [l][D][4D]
__device__ __half g_wte16  [(size_t)VOCAB*DMODEL];     // [V][D]

// ---------------- helpers ----------------
__device__ __forceinline__ float warp_max(float v){
    #pragma unroll
    for(int o=16;o;o>>=1) v = fmaxf(v, __shfl_xor_sync(0xffffffffu, v, o));
    return v;
}
__device__ __forceinline__ float warp_sum(float v){
    #pragma unroll
    for(int o=16;o;o>>=1) v += __shfl_xor_sync(0xffffffffu, v, o);
    return v;
}
__device__ __forceinline__ float gelu_exact(float v){
    return 0.5f * v * (1.0f + erff(v * 0.70710678118654752440f));
}
__device__ __forceinline__ void cp16(unsigned dst, const void* src, bool pred){
    int bytes = pred ? 16 : 0;
    asm volatile("cp.async.cg.shared.global [%0], [%1], 16, %2;\n"
                 :: "r"(dst), "l"(src), "r"(bytes));
}
#define CP_COMMIT() asm volatile("cp.async.commit_group;\n" ::: "memory")
#define CP_WAIT1()  asm volatile("cp.async.wait_group 1;\n" ::: "memory")

__device__ __forceinline__ void ldsm4(unsigned r[4], unsigned addr){
    asm volatile("ldmatrix.sync.aligned.m8n8.x4.shared.b16 {%0,%1,%2,%3}, [%4];"
                 : "=r"(r[0]),"=r"(r[1]),"=r"(r[2]),"=r"(r[3]) : "r"(addr));
}
__device__ __forceinline__ void mma_f16(float c[4], const unsigned a[4], const unsigned b[2]){
    asm volatile(
        "mma.sync.aligned.m16n8k16.row.col.f32.f16.f16.f32 "
        "{%0,%1,%2,%3}, {%4,%5,%6,%7}, {%8,%9}, {%0,%1,%2,%3};\n"
        : "+f"(c[0]), "+f"(c[1]), "+f"(c[2]), "+f"(c[3])
        : "r"(a[0]), "r"(a[1]), "r"(a[2]), "r"(a[3]), "r"(b[0]), "r"(b[1]));
}

// ---------------- weight prep: transpose fp32 [K][N] -> fp16 [N][K] ----------------
__global__ void transpose_to_half(const float* __restrict__ src, __half* __restrict__ dst,
                                  int K, int N)
{
    __shared__ float t[32][33];
    const size_t lsz = (size_t)K * N;
    src += blockIdx.z * lsz;
    dst += blockIdx.z * lsz;
    int n0 = blockIdx.x * 32, k0 = blockIdx.y * 32;
    int tx = threadIdx.x, ty = threadIdx.y;     // 32 x 8
    #pragma unroll
    for (int i = 0; i < 32; i += 8)
        t[ty+i][tx] = src[(size_t)(k0+ty+i)*N + n0+tx];
    __syncthreads();
    #pragma unroll
    for (int i = 0; i < 32; i += 8)
        dst[(size_t)(n0+ty+i)*K + k0+tx] = __float2half(t[tx][ty+i]);
}

// straight convert (wte already [V][D] = [N][K])
__global__ void convert_to_half(const float* __restrict__ src, __half* __restrict__ dst,
                                size_t n4)
{
    size_t i = (size_t)blockIdx.x * blockDim.x + threadIdx.x;
    if (i >= n4) return;
    float4 v = *(const float4*)(src + i*4);
    __half2* d2 = (__half2*)(dst + i*4);
    d2[0] = __floats2half2_rn(v.x, v.y);
    d2[1] = __floats2half2_rn(v.z, v.w);
}

// ---------------- embedding ----------------
__global__ void embed_kernel(const int* __restrict__ ids,
                             const float* __restrict__ wte,
                             const float* __restrict__ wpe,
                             float* __restrict__ x)
{
    int i = blockIdx.x * blockDim.x + threadIdx.x;
    if (i >= MROWS*DMODEL) return;
    int row = i / DMODEL;
    int d   = i - row*DMODEL;
    int t   = row & (TMAXS-1);
    int id  = ids[row];
    x[i] = wte[(size_t)id*DMODEL + d] + wpe[(size_t)t*DMODEL + d];
}

// ---------------- layernorm: fp32 in -> fp16 out ----------------
__global__ void layernorm_kernel(const float* __restrict__ in,
                                 __half* __restrict__ out,
                                 const float* __restrict__ g,
                                 const float* __restrict__ b)
{
    int row = blockIdx.x;
    const float* x = in + (size_t)row*DMODEL;
    float s = 0.f, ss = 0.f;
    for (int i = threadIdx.x; i < DMODEL; i += 256){
        float v = x[i]; s += v; ss += v*v;
    }
    __shared__ float sbuf[8], sbuf2[8];
    s  = warp_sum(s);
    ss = warp_sum(ss);
    if ((threadIdx.x & 31) == 0){ sbuf[threadIdx.x>>5] = s; sbuf2[threadIdx.x>>5] = ss; }
    __syncthreads();
    if (threadIdx.x == 0){
        float S=0.f, SS=0.f;
        #pragma unroll
        for (int i=0;i<8;i++){ S += sbuf[i]; SS += sbuf2[i]; }
        sbuf[0]  = S * (1.0f/DMODEL);
        sbuf2[0] = SS * (1.0f/DMODEL);
    }
    __syncthreads();
    float mean = sbuf[0];
    float var  = sbuf2[0] - mean*mean;
    float rstd = rsqrtf(var + 1e-5f);
    __half* o = out + (size_t)row*DMODEL;
    for (int i = threadIdx.x; i < DMODEL; i += 256)
        o[i] = __float2half((x[i]-mean)*rstd*g[i] + b[i]);
}

// =====================================================================
// fp16 NT GEMM: C[M,N] = A[M,K] @ Bt[N,K]^T,  fp32 accumulate.
// EPI: 0 none->fp32 (bounds on N), 1 +bias->fp32, 2 +bias+resid->fp32,
//      3 +bias+gelu->fp16
// Block 128x128, ktile 32 halves, 256 thr, 8 warps (2x4), warp 64x32.
// SMEM: As/Bs [2][128][40] halves (stride 40 -> conflict-free).
// =====================================================================
#define ROWP 40   // halves per row (32 + 8 pad); 80 bytes

template<int EPI, bool BOUND>
__global__ __launch_bounds__(256, 2) void gemm16(
    const __half* __restrict__ A, const __half* __restrict__ Bt,
    const float* __restrict__ bias, const float* __restrict__ resid,
    void* __restrict__ Cv, int M, int N, int K)
{
    __shared__ __half As[2][128][ROWP];
    __shared__ __half Bs[2][128][ROWP];

    const int tid  = threadIdx.x;
    const int lane = tid & 31;
    const int warp = tid >> 5;
    const int wm   = warp >> 2;
    const int wn   = warp & 3;
    const int bm   = blockIdx.y * 128;
    const int bn   = blockIdx.x * 128;
    const int T    = K / 32;

    const unsigned sA = (unsigned)__cvta_generic_to_shared(&As[0][0][0]);
    const unsigned sB = (unsigned)__cvta_generic_to_shared(&Bs[0][0][0]);
    const unsigned BUFB = 128*ROWP*2;   // bytes per buffer

    auto ldgsts = [&](int t, int buf){
        const int k0 = t*32;
        #pragma unroll
        for (int p = 0; p < 2; p++){
            int j = tid + p*256;
            int row = j >> 2, ch = j & 3;
            cp16(sA + buf*BUFB + row*(ROWP*2) + ch*16,
                 A + (size_t)(bm+row)*K + k0 + ch*8, true);
        }
        #pragma unroll
        for (int p = 0; p < 2; p++){
            int j = tid + p*256;
            int row = j >> 2, ch = j & 3;
            bool ok = !BOUND || (bn + row) < N;
            const __half* src = ok ? (Bt + (size_t)(bn+row)*K + k0 + ch*8) : Bt;
            cp16(sB + buf*BUFB + row*(ROWP*2) + ch*16, src, ok);
        }
    };

    float acc[4][4][4];
    #pragma unroll
    for (int i=0;i<4;i++)
        #pragma unroll
        for (int j=0;j<4;j++)
            #pragma unroll
            for (int r=0;r<4;r++) acc[i][j][r]=0.f;

    ldgsts(0, 0);
    CP_COMMIT();

    for (int t = 0; t < T; t++){
        const int buf = t & 1;
        if (t + 1 < T) ldgsts(t+1, (t+1)&1);
        CP_COMMIT();
        CP_WAIT1();
        __syncthreads();

        const unsigned a_base = sA + buf*BUFB
            + (wm*64 + (lane&15))*(ROWP*2) + ((lane>>4)<<4);

        #pragma unroll
        for (int ks = 0; ks < 2; ks++){
            const int kk = ks*16;
            unsigned af[4][4];
            #pragma unroll
            for (int mt = 0; mt < 4; mt++)
                ldsm4(af[mt], a_base + mt*16*(ROWP*2) + kk*2);
            unsigned bf[4][2];
            #pragma unroll
            for (int nt = 0; nt < 4; nt++){
                int n = wn*32 + nt*8 + (lane>>2);
                const __half* bp = &Bs[buf][n][kk + (lane&3)*2];
                bf[nt][0] = *(const unsigned*)bp;
                bf[nt][1] = *(const unsigned*)(bp + 8);
            }
            #pragma unroll
            for (int mt = 0; mt < 4; mt++)
                #pragma unroll
                for (int nt = 0; nt < 4; nt++)
                    mma_f16(acc[mt][nt], af[mt], bf[nt]);
        }
        __syncthreads();
    }

    // epilogue
    #pragma unroll
    for (int mt = 0; mt < 4; mt++){
        #pragma unroll
        for (int nt = 0; nt < 4; nt++){
            int col  = bn + wn*32 + nt*8 + 2*(lane&3);
            int row0 = bm + wm*64 + mt*16 + (lane>>2);
            float b0 = 0.f, b1 = 0.f;
            if (EPI >= 1){ b0 = bias[col]; b1 = bias[col+1]; }
            #pragma unroll
            for (int half = 0; half < 2; half++){
                int row = row0 + half*8;
                float v0 = acc[mt][nt][half*2+0] + b0;
                float v1 = acc[mt][nt][half*2+1] + b1;
                if (EPI == 2){
                    const float* rr = resid + (size_t)row*N + col;
                    v0 += rr[0]; v1 += rr[1];
                }
                if (EPI == 3){
                    v0 = gelu_exact(v0); v1 = gelu_exact(v1);
                    __half2 hv = __floats2half2_rn(v0, v1);
                    *(__half2*)((__half*)Cv + (size_t)row*N + col) = hv;
                } else if (EPI == 0){
                    float* C = (float*)Cv;
                    if (!BOUND || col   < N) C[(size_t)row*N + col]     = v0;
                    if (!BOUND || col+1 < N) C[(size_t)row*N + col + 1] = v1;
                } else {
                    *(float2*)((float*)Cv + (size_t)row*N + col) = make_float2(v0, v1);
                }
            }
        }
    }
}

// ---------------- attention: fp32 qkv in, fp16 y out ----------------
__global__ __launch_bounds__(128) void attention_kernel(
    const float* __restrict__ qkv, __half* __restrict__ y)
{
    const int tq = blockIdx.x;
    const int h  = blockIdx.y;
    const int b  = blockIdx.z;
    const int tid = threadIdx.x;

    __shared__ float sq[HD];
    __shared__ float sp[TMAXS];
    __shared__ float rmax[4], rsum[4];
    __shared__ float yc[HD];

    const size_t rowbase = (size_t)(b*TMAXS + tq) * (3*DMODEL);
    if (tid < HD) sq[tid] = qkv[rowbase + h*HD + tid];
    __syncthreads();

    const int nk = tq + 1;

    float lmax = -INFINITY;
    for (int k = tid; k < nk; k += 128){
        const float* kr = qkv + (size_t)(b*TMAXS + k)*(3*DMODEL) + DMODEL + h*HD;
        float dot = 0.f;
        #pragma unroll
        for (int d = 0; d < HD; d += 4){
            float4 kv = *(const float4*)(kr + d);
            dot += sq[d]*kv.x + sq[d+1]*kv.y + sq[d+2]*kv.z + sq[d+3]*kv.w;
        }
        dot *= 0.125f;
        sp[k] = dot;
        lmax = fmaxf(lmax, dot);
    }
    float wmx = warp_max(lmax);
    if ((tid & 31) == 0) rmax[tid>>5] = wmx;
    __syncthreads();
    float gmax = fmaxf(fmaxf(rmax[0],rmax[1]), fmaxf(rmax[2],rmax[3]));

    float lsum = 0.f;
    for (int k = tid; k < nk; k += 128){
        float e = __expf(sp[k] - gmax);
        sp[k] = e;
        lsum += e;
    }
    float ws = warp_sum(lsum);
    if ((tid & 31) == 0) rsum[tid>>5] = ws;
    __syncthreads();
    float inv = 1.0f / (rsum[0]+rsum[1]+rsum[2]+rsum[3]);

    const int d    = tid & 63;
    const int half = tid >> 6;
    float acc = 0.f;
    for (int k = half; k < nk; k += 2){
        acc += sp[k] * qkv[(size_t)(b*TMAXS + k)*(3*DMODEL) + 2*DMODEL + h*HD + d];
    }
    if (half) yc[d] = acc;
    __syncthreads();
    if (!half)
        y[(size_t)(b*TMAXS + tq)*DMODEL + h*HD + d] = __float2half((acc + yc[d]) * inv);
}

// ---------------- host orchestration ----------------
extern "C" void kernel_launch(void* const* d_in, const int* in_sizes, int n_in,
                              void* d_out, int out_size)
{
    const int*   ids    = (const int*)  d_in[0];
    const float* wte    = (const float*)d_in[1];
    const float* wpe    = (const float*)d_in[2];
    const float* ln1_g  = (const float*)d_in[3];
    const float* ln1_b  = (const float*)d_in[4];
    const float* attn_w = (const float*)d_in[5];
    const float* attn_b = (const float*)d_in[6];
    const float* proj_w = (const float*)d_in[7];
    const float* proj_b = (const float*)d_in[8];
    const float* ln2_g  = (const float*)d_in[9];
    const float* ln2_b  = (const float*)d_in[10];
    const float* fc_w   = (const float*)d_in[11];
    const float* fc_b   = (const float*)d_in[12];
    const float* fc2_w  = (const float*)d_in[13];
    const float* fc2_b  = (const float*)d_in[14];
    const float* lnf_g  = (const float*)d_in[15];
    const float* lnf_b  = (const float*)d_in[16];
    float* out = (float*)d_out;

    float  *x, *qkv;
    __half *h16, *y16, *fc16, *wq16, *wp16, *wf16, *wf216, *wte16;
    cudaGetSymbolAddress((void**)&x,    g_x);
    cudaGetSymbolAddress((void**)&qkv,  g_qkv);
    cudaGetSymbolAddress((void**)&h16,  g_h16);
    cudaGetSymbolAddress((void**)&y16,  g_y16);
    cudaGetSymbolAddress((void**)&fc16, g_fc16);
    cudaGetSymbolAddress((void**)&wq16, g_wqkv16);
    cudaGetSymbolAddress((void**)&wp16, g_wproj16);
    cudaGetSymbolAddress((void**)&wf16, g_wfc16);
    cudaGetSymbolAddress((void**)&wf216,g_wfc216);
    cudaGetSymbolAddress((void**)&wte16,g_wte16);

    // ---- weight prep (runs every forward; deterministic) ----
    {
        dim3 blk(32, 8);
        transpose_to_half<<<dim3(3*DMODEL/32, DMODEL/32, LAYERS), blk>>>(attn_w, wq16, DMODEL, 3*DMODEL);
        transpose_to_half<<<dim3(DMODEL/32,   DMODEL/32, LAYERS), blk>>>(proj_w, wp16, DMODEL, DMODEL);
        transpose_to_half<<<dim3(4*DMODEL/32, DMODEL/32, LAYERS), blk>>>(fc_w,   wf16, DMODEL, 4*DMODEL);
        transpose_to_half<<<dim3(DMODEL/32, 4*DMODEL/32, LAYERS), blk>>>(fc2_w,  wf216, 4*DMODEL, DMODEL);
        size_t n4 = (size_t)VOCAB*DMODEL/4;
        convert_to_half<<<(unsigned)((n4 + 255)/256), 256>>>(wte, wte16, n4);
    }

    embed_kernel<<<(MROWS*DMODEL + 255)/256, 256>>>(ids, wte, wpe, x);

    for (int l = 0; l < LAYERS; l++){
        layernorm_kernel<<<MROWS, 256>>>(x, h16, ln1_g + l*DMODEL, ln1_b + l*DMODEL);

        gemm16<1,false><<<dim3(3*DMODEL/128, MROWS/128), 256>>>(
            h16, wq16 + (size_t)l*3*DMODEL*DMODEL, attn_b + (size_t)l*3*DMODEL,
            nullptr, qkv, MROWS, 3*DMODEL, DMODEL);

        attention_kernel<<<dim3(TMAXS, NHEAD, BATCH), 128>>>(qkv, y16);

        gemm16<2,false><<<dim3(DMODEL/128, MROWS/128), 256>>>(
            y16, wp16 + (size_t)l*DMODEL*DMODEL, proj_b + (size_t)l*DMODEL,
            x, x, MROWS, DMODEL, DMODEL);

        layernorm_kernel<<<MROWS, 256>>>(x, h16, ln2_g + l*DMODEL, ln2_b + l*DMODEL);

        gemm16<3,false><<<dim3(4*DMODEL/128, MROWS/128), 256>>>(
            h16, wf16 + (size_t)l*4*DMODEL*DMODEL, fc_b + (size_t)l*4*DMODEL,
            nullptr, fc16, MROWS, 4*DMODEL, DMODEL);

        gemm16<2,false><<<dim3(DMODEL/128, MROWS/128), 256>>>(
            fc16, wf216 + (size_t)l*DMODEL*4*DMODEL, fc2_b + (size_t)l*DMODEL,
            x, x, MROWS, DMODEL, 4*DMODEL);
    }

    layernorm_kernel<<<MROWS, 256>>>(x, h16, lnf_g, lnf_b);

    gemm16<0,true><<<dim3((VOCAB + 127)/128, MROWS/128), 256>>>(
        h16, wte16, nullptr, nullptr, out, MROWS, VOCAB, DMODEL);
}

// round 8
// speedup vs baseline: 2.3827x; 2.0470x over previous
#include <cuda_runtime.h>
#include <cuda_fp16.h>
#include <math.h>
#include <cstdint>

// ---------------- problem constants ----------------
#define LAYERS 12
#define DMODEL 768
#define NHEAD  12
#define HD     64
#define TMAXS  1024
#define BATCH  2
#define MROWS  (BATCH*TMAXS)   // 2048
#define VOCAB  50257

// ---------------- scratch (static device memory; no allocation) ----------------
__device__ float  g_x  [MROWS*DMODEL];            // residual stream (fp32)
__device__ float  g_qkv[MROWS*3*DMODEL];          // qkv (fp32, for attention)
__device__ __half g_h16 [MROWS*DMODEL];           // LN outputs (fp16)
__device__ __half g_y16 [MROWS*DMODEL];           // attention out (fp16)
__device__ __half g_fc16[MROWS*4*DMODEL];         // gelu(fc) out (fp16)
__device__ __half g_wqkv16 [LAYERS*3*DMODEL*DMODEL];   // [l][3D][D]
__device__ __half g_wproj16[LAYERS*DMODEL*DMODEL];     // [l][D][D]
__device__ __half g_wfc16  [LAYERS*4*DMODEL*DMODEL];   // [l][4D][D]
__device__ __half g_wfc216 [LAYERS*DMODEL*4*DMODEL];   // [l][D][4D]
__device__ __half g_wte16  [(size_t)VOCAB*DMODEL];     // [V][D]

// ---------------- helpers ----------------
__device__ __forceinline__ float warp_sum(float v){
    #pragma unroll
    for(int o=16;o;o>>=1) v += __shfl_xor_sync(0xffffffffu, v, o);
    return v;
}
__device__ __forceinline__ float gelu_exact(float v){
    return 0.5f * v * (1.0f + erff(v * 0.70710678118654752440f));
}
__device__ __forceinline__ void cp16(unsigned dst, const void* src, bool pred){
    int bytes = pred ? 16 : 0;
    asm volatile("cp.async.cg.shared.global [%0], [%1], 16, %2;\n"
                 :: "r"(dst), "l"(src), "r"(bytes));
}
#define CP_COMMIT() asm volatile("cp.async.commit_group;\n" ::: "memory")
#define CP_WAIT1()  asm volatile("cp.async.wait_group 1;\n" ::: "memory")

__device__ __forceinline__ void ldsm4(unsigned r[4], unsigned addr){
    asm volatile("ldmatrix.sync.aligned.m8n8.x4.shared.b16 {%0,%1,%2,%3}, [%4];"
                 : "=r"(r[0]),"=r"(r[1]),"=r"(r[2]),"=r"(r[3]) : "r"(addr));
}
__device__ __forceinline__ void mma_f16(float c[4], const unsigned a[4], const unsigned b[2]){
    asm volatile(
        "mma.sync.aligned.m16n8k16.row.col.f32.f16.f16.f32 "
        "{%0,%1,%2,%3}, {%4,%5,%6,%7}, {%8,%9}, {%0,%1,%2,%3};\n"
        : "+f"(c[0]), "+f"(c[1]), "+f"(c[2]), "+f"(c[3])
        : "r"(a[0]), "r"(a[1]), "r"(a[2]), "r"(a[3]), "r"(b[0]), "r"(b[1]));
}

// ---------------- weight prep: transpose fp32 [K][N] -> fp16 [N][K] ----------------
__global__ void transpose_to_half(const float* __restrict__ src, __half* __restrict__ dst,
                                  int K, int N)
{
    __shared__ float t[32][33];
    const size_t lsz = (size_t)K * N;
    src += blockIdx.z * lsz;
    dst += blockIdx.z * lsz;
    int n0 = blockIdx.x * 32, k0 = blockIdx.y * 32;
    int tx = threadIdx.x, ty = threadIdx.y;     // 32 x 8
    #pragma unroll
    for (int i = 0; i < 32; i += 8)
        t[ty+i][tx] = src[(size_t)(k0+ty+i)*N + n0+tx];
    __syncthreads();
    #pragma unroll
    for (int i = 0; i < 32; i += 8)
        dst[(size_t)(n0+ty+i)*K + k0+tx] = __float2half(t[tx][ty+i]);
}

// straight convert (wte already [V][D] = [N][K])
__global__ void convert_to_half(const float* __restrict__ src, __half* __restrict__ dst,
                                size_t n4)
{
    size_t i = (size_t)blockIdx.x * blockDim.x + threadIdx.x;
    if (i >= n4) return;
    float4 v = *(const float4*)(src + i*4);
    __half2* d2 = (__half2*)(dst + i*4);
    d2[0] = __floats2half2_rn(v.x, v.y);
    d2[1] = __floats2half2_rn(v.z, v.w);
}

// ---------------- embedding ----------------
__global__ void embed_kernel(const int* __restrict__ ids,
                             const float* __restrict__ wte,
                             const float* __restrict__ wpe,
                             float* __restrict__ x)
{
    int i = blockIdx.x * blockDim.x + threadIdx.x;
    if (i >= MROWS*DMODEL) return;
    int row = i / DMODEL;
    int d   = i - row*DMODEL;
    int t   = row & (TMAXS-1);
    int id  = ids[row];
    x[i] = wte[(size_t)id*DMODEL + d] + wpe[(size_t)t*DMODEL + d];
}

// ---------------- layernorm: fp32 in -> fp16 out ----------------
__global__ void layernorm_kernel(const float* __restrict__ in,
                                 __half* __restrict__ out,
                                 const float* __restrict__ g,
                                 const float* __restrict__ b)
{
    int row = blockIdx.x;
    const float* x = in + (size_t)row*DMODEL;
    float s = 0.f, ss = 0.f;
    for (int i = threadIdx.x; i < DMODEL; i += 256){
        float v = x[i]; s += v; ss += v*v;
    }
    __shared__ float sbuf[8], sbuf2[8];
    s  = warp_sum(s);
    ss = warp_sum(ss);
    if ((threadIdx.x & 31) == 0){ sbuf[threadIdx.x>>5] = s; sbuf2[threadIdx.x>>5] = ss; }
    __syncthreads();
    if (threadIdx.x == 0){
        float S=0.f, SS=0.f;
        #pragma unroll
        for (int i=0;i<8;i++){ S += sbuf[i]; SS += sbuf2[i]; }
        sbuf[0]  = S * (1.0f/DMODEL);
        sbuf2[0] = SS * (1.0f/DMODEL);
    }
    __syncthreads();
    float mean = sbuf[0];
    float var  = sbuf2[0] - mean*mean;
    float rstd = rsqrtf(var + 1e-5f);
    __half* o = out + (size_t)row*DMODEL;
    for (int i = threadIdx.x; i < DMODEL; i += 256)
        o[i] = __float2half((x[i]-mean)*rstd*g[i] + b[i]);
}

// =====================================================================
// fp16 NT GEMM (unchanged from R7)
// =====================================================================
#define ROWP 40

template<int EPI, bool BOUND>
__global__ __launch_bounds__(256, 2) void gemm16(
    const __half* __restrict__ A, const __half* __restrict__ Bt,
    const float* __restrict__ bias, const float* __restrict__ resid,
    void* __restrict__ Cv, int M, int N, int K)
{
    __shared__ __half As[2][128][ROWP];
    __shared__ __half Bs[2][128][ROWP];

    const int tid  = threadIdx.x;
    const int lane = tid & 31;
    const int warp = tid >> 5;
    const int wm   = warp >> 2;
    const int wn   = warp & 3;
    const int bm   = blockIdx.y * 128;
    const int bn   = blockIdx.x * 128;
    const int T    = K / 32;

    const unsigned sA = (unsigned)__cvta_generic_to_shared(&As[0][0][0]);
    const unsigned sB = (unsigned)__cvta_generic_to_shared(&Bs[0][0][0]);
    const unsigned BUFB = 128*ROWP*2;

    auto ldgsts = [&](int t, int buf){
        const int k0 = t*32;
        #pragma unroll
        for (int p = 0; p < 2; p++){
            int j = tid + p*256;
            int row = j >> 2, ch = j & 3;
            cp16(sA + buf*BUFB + row*(ROWP*2) + ch*16,
                 A + (size_t)(bm+row)*K + k0 + ch*8, true);
        }
        #pragma unroll
        for (int p = 0; p < 2; p++){
            int j = tid + p*256;
            int row = j >> 2, ch = j & 3;
            bool ok = !BOUND || (bn + row) < N;
            const __half* src = ok ? (Bt + (size_t)(bn+row)*K + k0 + ch*8) : Bt;
            cp16(sB + buf*BUFB + row*(ROWP*2) + ch*16, src, ok);
        }
    };

    float acc[4][4][4];
    #pragma unroll
    for (int i=0;i<4;i++)
        #pragma unroll
        for (int j=0;j<4;j++)
            #pragma unroll
            for (int r=0;r<4;r++) acc[i][j][r]=0.f;

    ldgsts(0, 0);
    CP_COMMIT();

    for (int t = 0; t < T; t++){
        const int buf = t & 1;
        if (t + 1 < T) ldgsts(t+1, (t+1)&1);
        CP_COMMIT();
        CP_WAIT1();
        __syncthreads();

        const unsigned a_base = sA + buf*BUFB
            + (wm*64 + (lane&15))*(ROWP*2) + ((lane>>4)<<4);

        #pragma unroll
        for (int ks = 0; ks < 2; ks++){
            const int kk = ks*16;
            unsigned af[4][4];
            #pragma unroll
            for (int mt = 0; mt < 4; mt++)
                ldsm4(af[mt], a_base + mt*16*(ROWP*2) + kk*2);
            unsigned bf[4][2];
            #pragma unroll
            for (int nt = 0; nt < 4; nt++){
                int n = wn*32 + nt*8 + (lane>>2);
                const __half* bp = &Bs[buf][n][kk + (lane&3)*2];
                bf[nt][0] = *(const unsigned*)bp;
                bf[nt][1] = *(const unsigned*)(bp + 8);
            }
            #pragma unroll
            for (int mt = 0; mt < 4; mt++)
                #pragma unroll
                for (int nt = 0; nt < 4; nt++)
                    mma_f16(acc[mt][nt], af[mt], bf[nt]);
        }
        __syncthreads();
    }

    #pragma unroll
    for (int mt = 0; mt < 4; mt++){
        #pragma unroll
        for (int nt = 0; nt < 4; nt++){
            int col  = bn + wn*32 + nt*8 + 2*(lane&3);
            int row0 = bm + wm*64 + mt*16 + (lane>>2);
            float b0 = 0.f, b1 = 0.f;
            if (EPI >= 1){ b0 = bias[col]; b1 = bias[col+1]; }
            #pragma unroll
            for (int half = 0; half < 2; half++){
                int row = row0 + half*8;
                float v0 = acc[mt][nt][half*2+0] + b0;
                float v1 = acc[mt][nt][half*2+1] + b1;
                if (EPI == 2){
                    const float* rr = resid + (size_t)row*N + col;
                    v0 += rr[0]; v1 += rr[1];
                }
                if (EPI == 3){
                    v0 = gelu_exact(v0); v1 = gelu_exact(v1);
                    __half2 hv = __floats2half2_rn(v0, v1);
                    *(__half2*)((__half*)Cv + (size_t)row*N + col) = hv;
                } else if (EPI == 0){
                    float* C = (float*)Cv;
                    if (!BOUND || col   < N) C[(size_t)row*N + col]     = v0;
                    if (!BOUND || col+1 < N) C[(size_t)row*N + col + 1] = v1;
                } else {
                    *(float2*)((float*)Cv + (size_t)row*N + col) = make_float2(v0, v1);
                }
            }
        }
    }
}

// =====================================================================
// flash attention: block per (b, h, 64-query tile), online softmax.
// 256 threads: thread -> q = tid/4, sub-lane r = tid%3... r = tid&3.
// S phase: thread computes scores for k = r + 4j (j=0..15).
// O phase: thread accumulates d = r + 4dd (dd=0..15).
// SMEM tiles stride 68 floats (conflict-free; see analysis).
// =====================================================================
#define FA_T   64
#define FA_STR 68
#define FA_SMEM (4*FA_T*FA_STR*4)   // Q,K,V,P tiles

__global__ __launch_bounds__(256) void flash_attn(
    const float* __restrict__ qkv, __half* __restrict__ y)
{
    extern __shared__ float sm[];
    float* Qs = sm;
    float* Ks = Qs + FA_T*FA_STR;
    float* Vs = Ks + FA_T*FA_STR;
    float* Ps = Vs + FA_T*FA_STR;

    const int qt = gridDim.x - 1 - blockIdx.x;   // big tiles first
    const int h  = blockIdx.y;
    const int b  = blockIdx.z;
    const int tid  = threadIdx.x;
    const int qrow = tid >> 2;
    const int r    = tid & 3;
    const int q0   = qt * FA_T;

    const size_t base = (size_t)b*TMAXS*3*DMODEL + (size_t)h*HD;

    // load Q tile
    {
        const float* src = qkv + base + (size_t)(q0 + qrow)*3*DMODEL + r*16;
        float* dst = Qs + qrow*FA_STR + r*16;
        #pragma unroll
        for (int i=0;i<4;i++)
            *(float4*)(dst + 4*i) = *(const float4*)(src + 4*i);
    }

    float acc[16];
    #pragma unroll
    for (int i=0;i<16;i++) acc[i]=0.f;
    float m_run = -INFINITY, l_run = 0.f;
    const int q_glob = q0 + qrow;

    for (int kt = 0; kt <= qt; kt++){
        const int k0 = kt * FA_T;
        {
            const float* srck = qkv + base + DMODEL   + (size_t)(k0+qrow)*3*DMODEL + r*16;
            const float* srcv = qkv + base + 2*DMODEL + (size_t)(k0+qrow)*3*DMODEL + r*16;
            float* dk = Ks + qrow*FA_STR + r*16;
            float* dv = Vs + qrow*FA_STR + r*16;
            #pragma unroll
            for (int i=0;i<4;i++){
                *(float4*)(dk+4*i) = *(const float4*)(srck+4*i);
                *(float4*)(dv+4*i) = *(const float4*)(srcv+4*i);
            }
        }
        __syncthreads();

        // scores for my 16 k's
        float s[16];
        #pragma unroll
        for (int j=0;j<16;j++) s[j]=0.f;
        const float* qp = Qs + qrow*FA_STR;
        #pragma unroll 4
        for (int d=0; d<HD; d++){
            float qv = qp[d];
            #pragma unroll
            for (int j=0;j<16;j++)
                s[j] += qv * Ks[(r+4*j)*FA_STR + d];
        }
        const bool diag = (kt == qt);
        float tmax = -INFINITY;
        #pragma unroll
        for (int j=0;j<16;j++){
            s[j] *= 0.125f;
            if (diag && (k0 + r + 4*j) > q_glob) s[j] = -INFINITY;
            tmax = fmaxf(tmax, s[j]);
        }
        tmax = fmaxf(tmax, __shfl_xor_sync(0xffffffffu, tmax, 1));
        tmax = fmaxf(tmax, __shfl_xor_sync(0xffffffffu, tmax, 2));
        const float m_new = fmaxf(m_run, tmax);
        float lsum = 0.f;
        #pragma unroll
        for (int j=0;j<16;j++){
            float p = __expf(s[j] - m_new);   // exp(-inf)=0 for masked
            s[j] = p;
            lsum += p;
        }
        lsum += __shfl_xor_sync(0xffffffffu, lsum, 1);
        lsum += __shfl_xor_sync(0xffffffffu, lsum, 2);
        const float scale = __expf(m_run - m_new);
        m_run = m_new;
        l_run = l_run*scale + lsum;
        #pragma unroll
        for (int i=0;i<16;i++) acc[i] *= scale;

        #pragma unroll
        for (int j=0;j<16;j++)
            Ps[qrow*FA_STR + r + 4*j] = s[j];
        __syncthreads();

        // O update for my 16 d's
        const float* pp = Ps + qrow*FA_STR;
        #pragma unroll 4
        for (int k=0;k<FA_T;k++){
            float pv = pp[k];
            const float* vp = Vs + k*FA_STR + r;
            #pragma unroll
            for (int dd=0;dd<16;dd++)
                acc[dd] += pv * vp[4*dd];
        }
        __syncthreads();
    }

    const float inv = 1.0f / l_run;
    __half* dst = y + (size_t)(b*TMAXS + q_glob)*DMODEL + h*HD + r;
    #pragma unroll
    for (int dd=0;dd<16;dd++)
        dst[4*dd] = __float2half(acc[dd]*inv);
}

// ---------------- host orchestration ----------------
extern "C" void kernel_launch(void* const* d_in, const int* in_sizes, int n_in,
                              void* d_out, int out_size)
{
    const int*   ids    = (const int*)  d_in[0];
    const float* wte    = (const float*)d_in[1];
    const float* wpe    = (const float*)d_in[2];
    const float* ln1_g  = (const float*)d_in[3];
    const float* ln1_b  = (const float*)d_in[4];
    const float* attn_w = (const float*)d_in[5];
    const float* attn_b = (const float*)d_in[6];
    const float* proj_w = (const float*)d_in[7];
    const float* proj_b = (const float*)d_in[8];
    const float* ln2_g  = (const float*)d_in[9];
    const float* ln2_b  = (const float*)d_in[10];
    const float* fc_w   = (const float*)d_in[11];
    const float* fc_b   = (const float*)d_in[12];
    const float* fc2_w  = (const float*)d_in[13];
    const float* fc2_b  = (const float*)d_in[14];
    const float* lnf_g  = (const float*)d_in[15];
    const float* lnf_b  = (const float*)d_in[16];
    float* out = (float*)d_out;

    float  *x, *qkv;
    __half *h16, *y16, *fc16, *wq16, *wp16, *wf16, *wf216, *wte16;
    cudaGetSymbolAddress((void**)&x,    g_x);
    cudaGetSymbolAddress((void**)&qkv,  g_qkv);
    cudaGetSymbolAddress((void**)&h16,  g_h16);
    cudaGetSymbolAddress((void**)&y16,  g_y16);
    cudaGetSymbolAddress((void**)&fc16, g_fc16);
    cudaGetSymbolAddress((void**)&wq16, g_wqkv16);
    cudaGetSymbolAddress((void**)&wp16, g_wproj16);
    cudaGetSymbolAddress((void**)&wf16, g_wfc16);
    cudaGetSymbolAddress((void**)&wf216,g_wfc216);
    cudaGetSymbolAddress((void**)&wte16,g_wte16);

    cudaFuncSetAttribute(flash_attn, cudaFuncAttributeMaxDynamicSharedMemorySize, FA_SMEM);

    // ---- weight prep ----
    {
        dim3 blk(32, 8);
        transpose_to_half<<<dim3(3*DMODEL/32, DMODEL/32, LAYERS), blk>>>(attn_w, wq16, DMODEL, 3*DMODEL);
        transpose_to_half<<<dim3(DMODEL/32,   DMODEL/32, LAYERS), blk>>>(proj_w, wp16, DMODEL, DMODEL);
        transpose_to_half<<<dim3(4*DMODEL/32, DMODEL/32, LAYERS), blk>>>(fc_w,   wf16, DMODEL, 4*DMODEL);
        transpose_to_half<<<dim3(DMODEL/32, 4*DMODEL/32, LAYERS), blk>>>(fc2_w,  wf216, 4*DMODEL, DMODEL);
        size_t n4 = (size_t)VOCAB*DMODEL/4;
        convert_to_half<<<(unsigned)((n4 + 255)/256), 256>>>(wte, wte16, n4);
    }

    embed_kernel<<<(MROWS*DMODEL + 255)/256, 256>>>(ids, wte, wpe, x);

    for (int l = 0; l < LAYERS; l++){
        layernorm_kernel<<<MROWS, 256>>>(x, h16, ln1_g + l*DMODEL, ln1_b + l*DMODEL);

        gemm16<1,false><<<dim3(3*DMODEL/128, MROWS/128), 256>>>(
            h16, wq16 + (size_t)l*3*DMODEL*DMODEL, attn_b + (size_t)l*3*DMODEL,
            nullptr, qkv, MROWS, 3*DMODEL, DMODEL);

        flash_attn<<<dim3(TMAXS/FA_T, NHEAD, BATCH), 256, FA_SMEM>>>(qkv, y16);

        gemm16<2,false><<<dim3(DMODEL/128, MROWS/128), 256>>>(
            y16, wp16 + (size_t)l*DMODEL*DMODEL, proj_b + (size_t)l*DMODEL,
            x, x, MROWS, DMODEL, DMODEL);

        layernorm_kernel<<<MROWS, 256>>>(x, h16, ln2_g + l*DMODEL, ln2_b + l*DMODEL);

        gemm16<3,false><<<dim3(4*DMODEL/128, MROWS/128), 256>>>(
            h16, wf16 + (size_t)l*4*DMODEL*DMODEL, fc_b + (size_t)l*4*DMODEL,
            nullptr, fc16, MROWS, 4*DMODEL, DMODEL);

        gemm16<2,false><<<dim3(DMODEL/128, MROWS/128), 256>>>(
            fc16, wf216 + (size_t)l*DMODEL*4*DMODEL, fc2_b + (size_t)l*DMODEL,
            x, x, MROWS, DMODEL, 4*DMODEL);
    }

    layernorm_kernel<<<MROWS, 256>>>(x, h16, lnf_g, lnf_b);

    gemm16<0,true><<<dim3((VOCAB + 127)/128, MROWS/128), 256>>>(
        h16, wte16, nullptr, nullptr, out, MROWS, VOCAB, DMODEL);
}

// round 9
// speedup vs baseline: 4.8785x; 2.0474x over previous
#include <cuda_runtime.h>
#include <cuda_fp16.h>
#include <math.h>
#include <cstdint>

// ---------------- problem constants ----------------
#define LAYERS 12
#define DMODEL 768
#define NHEAD  12
#define HD     64
#define TMAXS  1024
#define BATCH  2
#define MROWS  (BATCH*TMAXS)   // 2048
#define VOCAB  50257

// ---------------- scratch ----------------
__device__ float  g_x   [MROWS*DMODEL];           // residual stream (fp32)
__device__ __half g_qkv16[MROWS*3*DMODEL];        // qkv (fp16)
__device__ __half g_h16 [MROWS*DMODEL];
__device__ __half g_y16 [MROWS*DMODEL];
__device__ __half g_fc16[MROWS*4*DMODEL];
__device__ __half g_wqkv16 [LAYERS*3*DMODEL*DMODEL];
__device__ __half g_wproj16[LAYERS*DMODEL*DMODEL];
__device__ __half g_wfc16  [LAYERS*4*DMODEL*DMODEL];
__device__ __half g_wfc216 [LAYERS*DMODEL*4*DMODEL];
__device__ __half g_wte16  [(size_t)VOCAB*DMODEL];

// ---------------- helpers ----------------
__device__ __forceinline__ float warp_sum(float v){
    #pragma unroll
    for(int o=16;o;o>>=1) v += __shfl_xor_sync(0xffffffffu, v, o);
    return v;
}
__device__ __forceinline__ float gelu_exact(float v){
    return 0.5f * v * (1.0f + erff(v * 0.70710678118654752440f));
}
__device__ __forceinline__ void cp16(unsigned dst, const void* src, bool pred){
    int bytes = pred ? 16 : 0;
    asm volatile("cp.async.cg.shared.global [%0], [%1], 16, %2;\n"
                 :: "r"(dst), "l"(src), "r"(bytes));
}
#define CP_COMMIT() asm volatile("cp.async.commit_group;\n" ::: "memory")
#define CP_WAIT0()  asm volatile("cp.async.wait_group 0;\n" ::: "memory")
#define CP_WAIT1()  asm volatile("cp.async.wait_group 1;\n" ::: "memory")

__device__ __forceinline__ void ldsm4(unsigned r[4], unsigned addr){
    asm volatile("ldmatrix.sync.aligned.m8n8.x4.shared.b16 {%0,%1,%2,%3}, [%4];"
                 : "=r"(r[0]),"=r"(r[1]),"=r"(r[2]),"=r"(r[3]) : "r"(addr));
}
__device__ __forceinline__ void ldsm4t(unsigned r[4], unsigned addr){
    asm volatile("ldmatrix.sync.aligned.m8n8.x4.trans.shared.b16 {%0,%1,%2,%3}, [%4];"
                 : "=r"(r[0]),"=r"(r[1]),"=r"(r[2]),"=r"(r[3]) : "r"(addr));
}
__device__ __forceinline__ void mma_f16(float c[4], const unsigned a[4], const unsigned b[2]){
    asm volatile(
        "mma.sync.aligned.m16n8k16.row.col.f32.f16.f16.f32 "
        "{%0,%1,%2,%3}, {%4,%5,%6,%7}, {%8,%9}, {%0,%1,%2,%3};\n"
        : "+f"(c[0]), "+f"(c[1]), "+f"(c[2]), "+f"(c[3])
        : "r"(a[0]), "r"(a[1]), "r"(a[2]), "r"(a[3]), "r"(b[0]), "r"(b[1]));
}
__device__ __forceinline__ unsigned packh2(float a, float b){
    __half2 h = __floats2half2_rn(a, b);
    return *(unsigned*)&h;
}

// ---------------- weight prep ----------------
__global__ void transpose_to_half(const float* __restrict__ src, __half* __restrict__ dst,
                                  int K, int N)
{
    __shared__ float t[32][33];
    const size_t lsz = (size_t)K * N;
    src += blockIdx.z * lsz;
    dst += blockIdx.z * lsz;
    int n0 = blockIdx.x * 32, k0 = blockIdx.y * 32;
    int tx = threadIdx.x, ty = threadIdx.y;
    #pragma unroll
    for (int i = 0; i < 32; i += 8)
        t[ty+i][tx] = src[(size_t)(k0+ty+i)*N + n0+tx];
    __syncthreads();
    #pragma unroll
    for (int i = 0; i < 32; i += 8)
        dst[(size_t)(n0+ty+i)*K + k0+tx] = __float2half(t[tx][ty+i]);
}

__global__ void convert_to_half(const float* __restrict__ src, __half* __restrict__ dst,
                                size_t n4)
{
    size_t i = (size_t)blockIdx.x * blockDim.x + threadIdx.x;
    if (i >= n4) return;
    float4 v = *(const float4*)(src + i*4);
    __half2* d2 = (__half2*)(dst + i*4);
    d2[0] = __floats2half2_rn(v.x, v.y);
    d2[1] = __floats2half2_rn(v.z, v.w);
}

// ---------------- embedding ----------------
__global__ void embed_kernel(const int* __restrict__ ids,
                             const float* __restrict__ wte,
                             const float* __restrict__ wpe,
                             float* __restrict__ x)
{
    int i = blockIdx.x * blockDim.x + threadIdx.x;
    if (i >= MROWS*DMODEL) return;
    int row = i / DMODEL;
    int d   = i - row*DMODEL;
    int t   = row & (TMAXS-1);
    int id  = ids[row];
    x[i] = wte[(size_t)id*DMODEL + d] + wpe[(size_t)t*DMODEL + d];
}

// ---------------- layernorm ----------------
__global__ void layernorm_kernel(const float* __restrict__ in,
                                 __half* __restrict__ out,
                                 const float* __restrict__ g,
                                 const float* __restrict__ b)
{
    int row = blockIdx.x;
    const float* x = in + (size_t)row*DMODEL;
    float s = 0.f, ss = 0.f;
    for (int i = threadIdx.x; i < DMODEL; i += 256){
        float v = x[i]; s += v; ss += v*v;
    }
    __shared__ float sbuf[8], sbuf2[8];
    s  = warp_sum(s);
    ss = warp_sum(ss);
    if ((threadIdx.x & 31) == 0){ sbuf[threadIdx.x>>5] = s; sbuf2[threadIdx.x>>5] = ss; }
    __syncthreads();
    if (threadIdx.x == 0){
        float S=0.f, SS=0.f;
        #pragma unroll
        for (int i=0;i<8;i++){ S += sbuf[i]; SS += sbuf2[i]; }
        sbuf[0]  = S * (1.0f/DMODEL);
        sbuf2[0] = SS * (1.0f/DMODEL);
    }
    __syncthreads();
    float mean = sbuf[0];
    float var  = sbuf2[0] - mean*mean;
    float rstd = rsqrtf(var + 1e-5f);
    __half* o = out + (size_t)row*DMODEL;
    for (int i = threadIdx.x; i < DMODEL; i += 256)
        o[i] = __float2half((x[i]-mean)*rstd*g[i] + b[i]);
}

// =====================================================================
// fp16 NT GEMM (R7-proven).  EPI: 0 none->fp32(N-bounds), 2 +bias+resid->fp32,
// 3 +bias+gelu->fp16, 4 +bias->fp16
// =====================================================================
#define ROWP 40

template<int EPI, bool BOUND>
__global__ __launch_bounds__(256, 2) void gemm16(
    const __half* __restrict__ A, const __half* __restrict__ Bt,
    const float* __restrict__ bias, const float* __restrict__ resid,
    void* __restrict__ Cv, int M, int N, int K)
{
    __shared__ __half As[2][128][ROWP];
    __shared__ __half Bs[2][128][ROWP];

    const int tid  = threadIdx.x;
    const int lane = tid & 31;
    const int warp = tid >> 5;
    const int wm   = warp >> 2;
    const int wn   = warp & 3;
    const int bm   = blockIdx.y * 128;
    const int bn   = blockIdx.x * 128;
    const int T    = K / 32;

    const unsigned sA = (unsigned)__cvta_generic_to_shared(&As[0][0][0]);
    const unsigned sB = (unsigned)__cvta_generic_to_shared(&Bs[0][0][0]);
    const unsigned BUFB = 128*ROWP*2;

    auto ldgsts = [&](int t, int buf){
        const int k0 = t*32;
        #pragma unroll
        for (int p = 0; p < 2; p++){
            int j = tid + p*256;
            int row = j >> 2, ch = j & 3;
            cp16(sA + buf*BUFB + row*(ROWP*2) + ch*16,
                 A + (size_t)(bm+row)*K + k0 + ch*8, true);
        }
        #pragma unroll
        for (int p = 0; p < 2; p++){
            int j = tid + p*256;
            int row = j >> 2, ch = j & 3;
            bool ok = !BOUND || (bn + row) < N;
            const __half* src = ok ? (Bt + (size_t)(bn+row)*K + k0 + ch*8) : Bt;
            cp16(sB + buf*BUFB + row*(ROWP*2) + ch*16, src, ok);
        }
    };

    float acc[4][4][4];
    #pragma unroll
    for (int i=0;i<4;i++)
        #pragma unroll
        for (int j=0;j<4;j++)
            #pragma unroll
            for (int r=0;r<4;r++) acc[i][j][r]=0.f;

    ldgsts(0, 0);
    CP_COMMIT();

    for (int t = 0; t < T; t++){
        const int buf = t & 1;
        if (t + 1 < T) ldgsts(t+1, (t+1)&1);
        CP_COMMIT();
        CP_WAIT1();
        __syncthreads();

        const unsigned a_base = sA + buf*BUFB
            + (wm*64 + (lane&15))*(ROWP*2) + ((lane>>4)<<4);

        #pragma unroll
        for (int ks = 0; ks < 2; ks++){
            const int kk = ks*16;
            unsigned af[4][4];
            #pragma unroll
            for (int mt = 0; mt < 4; mt++)
                ldsm4(af[mt], a_base + mt*16*(ROWP*2) + kk*2);
            unsigned bf[4][2];
            #pragma unroll
            for (int nt = 0; nt < 4; nt++){
                int n = wn*32 + nt*8 + (lane>>2);
                const __half* bp = &Bs[buf][n][kk + (lane&3)*2];
                bf[nt][0] = *(const unsigned*)bp;
                bf[nt][1] = *(const unsigned*)(bp + 8);
            }
            #pragma unroll
            for (int mt = 0; mt < 4; mt++)
                #pragma unroll
                for (int nt = 0; nt < 4; nt++)
                    mma_f16(acc[mt][nt], af[mt], bf[nt]);
        }
        __syncthreads();
    }

    #pragma unroll
    for (int mt = 0; mt < 4; mt++){
        #pragma unroll
        for (int nt = 0; nt < 4; nt++){
            int col  = bn + wn*32 + nt*8 + 2*(lane&3);
            int row0 = bm + wm*64 + mt*16 + (lane>>2);
            float b0 = 0.f, b1 = 0.f;
            if (EPI >= 2){ b0 = bias[col]; b1 = bias[col+1]; }
            #pragma unroll
            for (int half = 0; half < 2; half++){
                int row = row0 + half*8;
                float v0 = acc[mt][nt][half*2+0] + b0;
                float v1 = acc[mt][nt][half*2+1] + b1;
                if (EPI == 2){
                    const float* rr = resid + (size_t)row*N + col;
                    v0 += rr[0]; v1 += rr[1];
                }
                if (EPI == 3){ v0 = gelu_exact(v0); v1 = gelu_exact(v1); }
                if (EPI == 3 || EPI == 4){
                    __half2 hv = __floats2half2_rn(v0, v1);
                    *(__half2*)((__half*)Cv + (size_t)row*N + col) = hv;
                } else if (EPI == 0){
                    float* C = (float*)Cv;
                    if (!BOUND || col   < N) C[(size_t)row*N + col]     = v0;
                    if (!BOUND || col+1 < N) C[(size_t)row*N + col + 1] = v1;
                } else {
                    *(float2*)((float*)Cv + (size_t)row*N + col) = make_float2(v0, v1);
                }
            }
        }
    }
}

// =====================================================================
// tensor-core flash attention.
// block = (qt, h, b); 128 thr / 4 warps; warp w owns q rows [16w,16w+16).
// fp16 qkv in; S=QK^T and O+=PV on mma.m16n8k16; softmax fp32 in regs.
// KV tiles 64x64 halves, row stride 72 (144B, ldsm conflict-free), cp.async
// double buffered.
// =====================================================================
#define FSTR 72          // halves per row
#define FTILEB (64*FSTR*2)  // 9216 bytes per tensor per buffer

__global__ __launch_bounds__(128, 3) void flash_attn16(
    const __half* __restrict__ qkv, __half* __restrict__ y)
{
    __shared__ __half sK[2][64*FSTR];
    __shared__ __half sV[2][64*FSTR];

    const int qt = gridDim.x - 1 - blockIdx.x;   // big tiles first
    const int h  = blockIdx.y;
    const int b  = blockIdx.z;
    const int tid  = threadIdx.x;
    const int lane = tid & 31;
    const int w    = tid >> 5;
    const int q0   = qt * 64;

    const unsigned skb = (unsigned)__cvta_generic_to_shared(&sK[0][0]);
    const unsigned svb = (unsigned)__cvta_generic_to_shared(&sV[0][0]);

    // ---- stage Q tile into sK[0], pull A-frags to registers ----
    {
        int row = tid >> 1, hf = tid & 1;
        const __half* src = qkv + (size_t)(b*TMAXS + q0 + row)*(3*DMODEL) + h*HD + hf*32;
        unsigned dst = skb + row*144 + hf*64;
        #pragma unroll
        for (int c = 0; c < 4; c++) cp16(dst + c*16, src + c*8, true);
        CP_COMMIT(); CP_WAIT0();
    }
    __syncthreads();
    unsigned qa[4][4];
    #pragma unroll
    for (int ks = 0; ks < 4; ks++)
        ldsm4(qa[ks], skb + (16*w + (lane&15))*144 + ((lane>>4)<<4) + ks*32);
    __syncthreads();

    auto stage = [&](int kt, int buf){
        int row = tid >> 1, hf = tid & 1;
        size_t roff = (size_t)(b*TMAXS + kt*64 + row)*(3*DMODEL) + h*HD;
        const __half* sk = qkv + roff + DMODEL   + hf*32;
        const __half* sv = qkv + roff + 2*DMODEL + hf*32;
        unsigned dk = skb + buf*FTILEB + row*144 + hf*64;
        unsigned dv = svb + buf*FTILEB + row*144 + hf*64;
        #pragma unroll
        for (int c = 0; c < 4; c++){
            cp16(dk + c*16, sk + c*8, true);
            cp16(dv + c*16, sv + c*8, true);
        }
    };

    float o[8][4];
    #pragma unroll
    for (int i=0;i<8;i++){ o[i][0]=0.f; o[i][1]=0.f; o[i][2]=0.f; o[i][3]=0.f; }
    float m0 = -INFINITY, m1 = -INFINITY, l0 = 0.f, l1 = 0.f;
    const int r0g = q0 + 16*w + (lane>>2);
    const int r1g = r0g + 8;

    stage(0, 0); CP_COMMIT();

    for (int kt = 0; kt <= qt; kt++){
        const int buf = kt & 1;
        if (kt < qt){ stage(kt+1, buf^1); CP_COMMIT(); CP_WAIT1(); }
        else        { CP_WAIT0(); }
        __syncthreads();

        // ---- S = Q @ K^T ----
        float s[8][4];
        #pragma unroll
        for (int i=0;i<8;i++){ s[i][0]=0.f; s[i][1]=0.f; s[i][2]=0.f; s[i][3]=0.f; }
        #pragma unroll
        for (int ks = 0; ks < 4; ks++){
            #pragma unroll
            for (int p = 0; p < 4; p++){
                unsigned bfr[4];
                ldsm4(bfr, skb + buf*FTILEB
                      + ((lane&7) + ((lane>>4)&1)*8 + 16*p)*144
                      + ((lane>>3)&1)*16 + ks*32);
                mma_f16(s[2*p],   qa[ks], &bfr[0]);
                mma_f16(s[2*p+1], qa[ks], &bfr[2]);
            }
        }

        // ---- online softmax (fp32, in regs) ----
        const bool diag = (kt == qt);
        float mx0 = -INFINITY, mx1 = -INFINITY;
        #pragma unroll
        for (int nt = 0; nt < 8; nt++){
            #pragma unroll
            for (int j = 0; j < 2; j++){
                int kg = kt*64 + 8*nt + 2*(lane&3) + j;
                float v0 = s[nt][j]   * 0.125f;
                float v1 = s[nt][2+j] * 0.125f;
                if (diag && kg > r0g) v0 = -INFINITY;
                if (diag && kg > r1g) v1 = -INFINITY;
                s[nt][j]   = v0;
                s[nt][2+j] = v1;
                mx0 = fmaxf(mx0, v0);
                mx1 = fmaxf(mx1, v1);
            }
        }
        mx0 = fmaxf(mx0, __shfl_xor_sync(0xffffffffu, mx0, 1));
        mx0 = fmaxf(mx0, __shfl_xor_sync(0xffffffffu, mx0, 2));
        mx1 = fmaxf(mx1, __shfl_xor_sync(0xffffffffu, mx1, 1));
        mx1 = fmaxf(mx1, __shfl_xor_sync(0xffffffffu, mx1, 2));
        const float mn0 = fmaxf(m0, mx0), mn1 = fmaxf(m1, mx1);
        const float e0 = __expf(m0 - mn0), e1 = __expf(m1 - mn1);
        m0 = mn0; m1 = mn1;
        float ls0 = 0.f, ls1 = 0.f;
        #pragma unroll
        for (int nt = 0; nt < 8; nt++){
            #pragma unroll
            for (int j = 0; j < 2; j++){
                float p0 = __expf(s[nt][j]   - mn0);
                float p1 = __expf(s[nt][2+j] - mn1);
                s[nt][j]   = p0;
                s[nt][2+j] = p1;
                ls0 += p0; ls1 += p1;
            }
        }
        ls0 += __shfl_xor_sync(0xffffffffu, ls0, 1);
        ls0 += __shfl_xor_sync(0xffffffffu, ls0, 2);
        ls1 += __shfl_xor_sync(0xffffffffu, ls1, 1);
        ls1 += __shfl_xor_sync(0xffffffffu, ls1, 2);
        l0 = l0*e0 + ls0;
        l1 = l1*e1 + ls1;
        #pragma unroll
        for (int dt = 0; dt < 8; dt++){
            o[dt][0] *= e0; o[dt][1] *= e0;
            o[dt][2] *= e1; o[dt][3] *= e1;
        }

        // ---- pack P to A-frags (C-frag layout == A-frag layout) ----
        unsigned pa[4][4];
        #pragma unroll
        for (int ks = 0; ks < 4; ks++){
            pa[ks][0] = packh2(s[2*ks][0],   s[2*ks][1]);
            pa[ks][1] = packh2(s[2*ks][2],   s[2*ks][3]);
            pa[ks][2] = packh2(s[2*ks+1][0], s[2*ks+1][1]);
            pa[ks][3] = packh2(s[2*ks+1][2], s[2*ks+1][3]);
        }

        // ---- O += P @ V  (B-frags via ldmatrix.trans on V[k][d]) ----
        #pragma unroll
        for (int ks = 0; ks < 4; ks++){
            #pragma unroll
            for (int p = 0; p < 4; p++){
                unsigned bfr[4];
                ldsm4t(bfr, svb + buf*FTILEB
                       + (16*ks + (lane&7) + ((lane>>3)&1)*8)*144
                       + (16*p + ((lane>>4)&1)*8)*2);
                mma_f16(o[2*p],   pa[ks], &bfr[0]);
                mma_f16(o[2*p+1], pa[ks], &bfr[2]);
            }
        }
        __syncthreads();
    }

    // ---- normalize + store fp16 ----
    const float i0 = 1.0f / l0, i1 = 1.0f / l1;
    __half* y0 = y + (size_t)(b*TMAXS + r0g)*DMODEL + h*HD + 2*(lane&3);
    __half* y1 = y + (size_t)(b*TMAXS + r1g)*DMODEL + h*HD + 2*(lane&3);
    #pragma unroll
    for (int dt = 0; dt < 8; dt++){
        *(__half2*)(y0 + 8*dt) = __floats2half2_rn(o[dt][0]*i0, o[dt][1]*i0);
        *(__half2*)(y1 + 8*dt) = __floats2half2_rn(o[dt][2]*i1, o[dt][3]*i1);
    }
}

// ---------------- host orchestration ----------------
extern "C" void kernel_launch(void* const* d_in, const int* in_sizes, int n_in,
                              void* d_out, int out_size)
{
    const int*   ids    = (const int*)  d_in[0];
    const float* wte    = (const float*)d_in[1];
    const float* wpe    = (const float*)d_in[2];
    const float* ln1_g  = (const float*)d_in[3];
    const float* ln1_b  = (const float*)d_in[4];
    const float* attn_w = (const float*)d_in[5];
    const float* attn_b = (const float*)d_in[6];
    const float* proj_w = (const float*)d_in[7];
    const float* proj_b = (const float*)d_in[8];
    const float* ln2_g  = (const float*)d_in[9];
    const float* ln2_b  = (const float*)d_in[10];
    const float* fc_w   = (const float*)d_in[11];
    const float* fc_b   = (const float*)d_in[12];
    const float* fc2_w  = (const float*)d_in[13];
    const float* fc2_b  = (const float*)d_in[14];
    const float* lnf_g  = (const float*)d_in[15];
    const float* lnf_b  = (const float*)d_in[16];
    float* out = (float*)d_out;

    float  *x;
    __half *qkv16, *h16, *y16, *fc16, *wq16, *wp16, *wf16, *wf216, *wte16;
    cudaGetSymbolAddress((void**)&x,     g_x);
    cudaGetSymbolAddress((void**)&qkv16, g_qkv16);
    cudaGetSymbolAddress((void**)&h16,   g_h16);
    cudaGetSymbolAddress((void**)&y16,   g_y16);
    cudaGetSymbolAddress((void**)&fc16,  g_fc16);
    cudaGetSymbolAddress((void**)&wq16,  g_wqkv16);
    cudaGetSymbolAddress((void**)&wp16,  g_wproj16);
    cudaGetSymbolAddress((void**)&wf16,  g_wfc16);
    cudaGetSymbolAddress((void**)&wf216, g_wfc216);
    cudaGetSymbolAddress((void**)&wte16, g_wte16);

    // ---- weight prep ----
    {
        dim3 blk(32, 8);
        transpose_to_half<<<dim3(3*DMODEL/32, DMODEL/32, LAYERS), blk>>>(attn_w, wq16, DMODEL, 3*DMODEL);
        transpose_to_half<<<dim3(DMODEL/32,   DMODEL/32, LAYERS), blk>>>(proj_w, wp16, DMODEL, DMODEL);
        transpose_to_half<<<dim3(4*DMODEL/32, DMODEL/32, LAYERS), blk>>>(fc_w,   wf16, DMODEL, 4*DMODEL);
        transpose_to_half<<<dim3(DMODEL/32, 4*DMODEL/32, LAYERS), blk>>>(fc2_w,  wf216, 4*DMODEL, DMODEL);
        size_t n4 = (size_t)VOCAB*DMODEL/4;
        convert_to_half<<<(unsigned)((n4 + 255)/256), 256>>>(wte, wte16, n4);
    }

    embed_kernel<<<(MROWS*DMODEL + 255)/256, 256>>>(ids, wte, wpe, x);

    for (int l = 0; l < LAYERS; l++){
        layernorm_kernel<<<MROWS, 256>>>(x, h16, ln1_g + l*DMODEL, ln1_b + l*DMODEL);

        gemm16<4,false><<<dim3(3*DMODEL/128, MROWS/128), 256>>>(
            h16, wq16 + (size_t)l*3*DMODEL*DMODEL, attn_b + (size_t)l*3*DMODEL,
            nullptr, qkv16, MROWS, 3*DMODEL, DMODEL);

        flash_attn16<<<dim3(TMAXS/64, NHEAD, BATCH), 128>>>(qkv16, y16);

        gemm16<2,false><<<dim3(DMODEL/128, MROWS/128), 256>>>(
            y16, wp16 + (size_t)l*DMODEL*DMODEL, proj_b + (size_t)l*DMODEL,
            x, x, MROWS, DMODEL, DMODEL);

        layernorm_kernel<<<MROWS, 256>>>(x, h16, ln2_g + l*DMODEL, ln2_b + l*DMODEL);

        gemm16<3,false><<<dim3(4*DMODEL/128, MROWS/128), 256>>>(
            h16, wf16 + (size_t)l*4*DMODEL*DMODEL, fc_b + (size_t)l*4*DMODEL,
            nullptr, fc16, MROWS, 4*DMODEL, DMODEL);

        gemm16<2,false><<<dim3(DMODEL/128, MROWS/128), 256>>>(
            fc16, wf216 + (size_t)l*DMODEL*4*DMODEL, fc2_b + (size_t)l*DMODEL,
            x, x, MROWS, DMODEL, 4*DMODEL);
    }

    layernorm_kernel<<<MROWS, 256>>>(x, h16, lnf_g, lnf_b);

    gemm16<0,true><<<dim3((VOCAB + 127)/128, MROWS/128), 256>>>(
        h16, wte16, nullptr, nullptr, out, MROWS, VOCAB, DMODEL);
}

// round 10
// speedup vs baseline: 5.1642x; 1.0586x over previous
#include <cuda_runtime.h>
#include <cuda_fp16.h>
#include <math.h>
#include <cstdint>

// ---------------- problem constants ----------------
#define LAYERS 12
#define DMODEL 768
#define NHEAD  12
#define HD     64
#define TMAXS  1024
#define BATCH  2
#define MROWS  (BATCH*TMAXS)   // 2048
#define VOCAB  50257

// ---------------- scratch ----------------
__device__ float  g_x   [MROWS*DMODEL];
__device__ __half g_qkv16[MROWS*3*DMODEL];
__device__ __half g_h16 [MROWS*DMODEL];
__device__ __half g_y16 [MROWS*DMODEL];
__device__ __half g_fc16[MROWS*4*DMODEL];
__device__ __half g_wqkv16 [LAYERS*3*DMODEL*DMODEL];
__device__ __half g_wproj16[LAYERS*DMODEL*DMODEL];
__device__ __half g_wfc16  [LAYERS*4*DMODEL*DMODEL];
__device__ __half g_wfc216 [LAYERS*DMODEL*4*DMODEL];
__device__ __half g_wte16  [(size_t)VOCAB*DMODEL];

// ---------------- helpers ----------------
__device__ __forceinline__ float warp_sum(float v){
    #pragma unroll
    for(int o=16;o;o>>=1) v += __shfl_xor_sync(0xffffffffu, v, o);
    return v;
}
__device__ __forceinline__ float gelu_exact(float v){
    return 0.5f * v * (1.0f + erff(v * 0.70710678118654752440f));
}
__device__ __forceinline__ void cp16(unsigned dst, const void* src, bool pred){
    int bytes = pred ? 16 : 0;
    asm volatile("cp.async.cg.shared.global [%0], [%1], 16, %2;\n"
                 :: "r"(dst), "l"(src), "r"(bytes));
}
#define CP_COMMIT() asm volatile("cp.async.commit_group;\n" ::: "memory")
#define CP_WAIT0()  asm volatile("cp.async.wait_group 0;\n" ::: "memory")
#define CP_WAIT1()  asm volatile("cp.async.wait_group 1;\n" ::: "memory")

__device__ __forceinline__ void ldsm4(unsigned r[4], unsigned addr){
    asm volatile("ldmatrix.sync.aligned.m8n8.x4.shared.b16 {%0,%1,%2,%3}, [%4];"
                 : "=r"(r[0]),"=r"(r[1]),"=r"(r[2]),"=r"(r[3]) : "r"(addr));
}
__device__ __forceinline__ void ldsm4t(unsigned r[4], unsigned addr){
    asm volatile("ldmatrix.sync.aligned.m8n8.x4.trans.shared.b16 {%0,%1,%2,%3}, [%4];"
                 : "=r"(r[0]),"=r"(r[1]),"=r"(r[2]),"=r"(r[3]) : "r"(addr));
}
__device__ __forceinline__ void mma_f16(float c[4], const unsigned a[4], const unsigned b[2]){
    asm volatile(
        "mma.sync.aligned.m16n8k16.row.col.f32.f16.f16.f32 "
        "{%0,%1,%2,%3}, {%4,%5,%6,%7}, {%8,%9}, {%0,%1,%2,%3};\n"
        : "+f"(c[0]), "+f"(c[1]), "+f"(c[2]), "+f"(c[3])
        : "r"(a[0]), "r"(a[1]), "r"(a[2]), "r"(a[3]), "r"(b[0]), "r"(b[1]));
}
__device__ __forceinline__ unsigned packh2(float a, float b){
    __half2 h = __floats2half2_rn(a, b);
    return *(unsigned*)&h;
}

// ---------------- weight prep ----------------
__global__ void transpose_to_half(const float* __restrict__ src, __half* __restrict__ dst,
                                  int K, int N)
{
    __shared__ float t[32][33];
    const size_t lsz = (size_t)K * N;
    src += blockIdx.z * lsz;
    dst += blockIdx.z * lsz;
    int n0 = blockIdx.x * 32, k0 = blockIdx.y * 32;
    int tx = threadIdx.x, ty = threadIdx.y;
    #pragma unroll
    for (int i = 0; i < 32; i += 8)
        t[ty+i][tx] = src[(size_t)(k0+ty+i)*N + n0+tx];
    __syncthreads();
    #pragma unroll
    for (int i = 0; i < 32; i += 8)
        dst[(size_t)(n0+ty+i)*K + k0+tx] = __float2half(t[tx][ty+i]);
}

__global__ void convert_to_half(const float* __restrict__ src, __half* __restrict__ dst,
                                size_t n4)
{
    size_t i = (size_t)blockIdx.x * blockDim.x + threadIdx.x;
    if (i >= n4) return;
    float4 v = *(const float4*)(src + i*4);
    __half2* d2 = (__half2*)(dst + i*4);
    d2[0] = __floats2half2_rn(v.x, v.y);
    d2[1] = __floats2half2_rn(v.z, v.w);
}

// ---------------- embedding ----------------
__global__ void embed_kernel(const int* __restrict__ ids,
                             const float* __restrict__ wte,
                             const float* __restrict__ wpe,
                             float* __restrict__ x)
{
    int i = blockIdx.x * blockDim.x + threadIdx.x;
    if (i >= MROWS*DMODEL) return;
    int row = i / DMODEL;
    int d   = i - row*DMODEL;
    int t   = row & (TMAXS-1);
    int id  = ids[row];
    x[i] = wte[(size_t)id*DMODEL + d] + wpe[(size_t)t*DMODEL + d];
}

// ---------------- layernorm ----------------
__global__ void layernorm_kernel(const float* __restrict__ in,
                                 __half* __restrict__ out,
                                 const float* __restrict__ g,
                                 const float* __restrict__ b)
{
    int row = blockIdx.x;
    const float* x = in + (size_t)row*DMODEL;
    float s = 0.f, ss = 0.f;
    for (int i = threadIdx.x; i < DMODEL; i += 256){
        float v = x[i]; s += v; ss += v*v;
    }
    __shared__ float sbuf[8], sbuf2[8];
    s  = warp_sum(s);
    ss = warp_sum(ss);
    if ((threadIdx.x & 31) == 0){ sbuf[threadIdx.x>>5] = s; sbuf2[threadIdx.x>>5] = ss; }
    __syncthreads();
    if (threadIdx.x == 0){
        float S=0.f, SS=0.f;
        #pragma unroll
        for (int i=0;i<8;i++){ S += sbuf[i]; SS += sbuf2[i]; }
        sbuf[0]  = S * (1.0f/DMODEL);
        sbuf2[0] = SS * (1.0f/DMODEL);
    }
    __syncthreads();
    float mean = sbuf[0];
    float var  = sbuf2[0] - mean*mean;
    float rstd = rsqrtf(var + 1e-5f);
    __half* o = out + (size_t)row*DMODEL;
    for (int i = threadIdx.x; i < DMODEL; i += 256)
        o[i] = __float2half((x[i]-mean)*rstd*g[i] + b[i]);
}

// =====================================================================
// fp16 NT GEMM, 3-stage cp.async pipeline, all-ldmatrix fragments.
// EPI: 0 none->fp32(N-bounds), 2 +bias+resid->fp32, 3 +bias+gelu->fp16,
//      4 +bias->fp16
// Block 128x128, ktile 32, 256 thr, 8 warps (2x4), warp 64x32.
// Dynamic SMEM: As/Bs [3][128][40] halves.
// =====================================================================
#define ROWP 40
#define G16_BUFB (128*ROWP*2)          // bytes per tensor per stage
#define G16_SMEM (6*G16_BUFB)          // 3 stages x (A+B) = 61440 B

template<int EPI, bool BOUND>
__global__ __launch_bounds__(256, 2) void gemm16(
    const __half* __restrict__ A, const __half* __restrict__ Bt,
    const float* __restrict__ bias, const float* __restrict__ resid,
    void* __restrict__ Cv, int M, int N, int K)
{
    extern __shared__ __half smem16[];
    __half* Bgen = smem16 + 3*128*ROWP;

    const int tid  = threadIdx.x;
    const int lane = tid & 31;
    const int warp = tid >> 5;
    const int wm   = warp >> 2;
    const int wn   = warp & 3;
    const int bm   = blockIdx.y * 128;
    const int bn   = blockIdx.x * 128;
    const int T    = K / 32;

    const unsigned sA = (unsigned)__cvta_generic_to_shared(smem16);
    const unsigned sB = (unsigned)__cvta_generic_to_shared(Bgen);

    auto ldgsts = [&](int t, int buf){
        const int k0 = t*32;
        #pragma unroll
        for (int p = 0; p < 2; p++){
            int j = tid + p*256;
            int row = j >> 2, ch = j & 3;
            cp16(sA + buf*G16_BUFB + row*(ROWP*2) + ch*16,
                 A + (size_t)(bm+row)*K + k0 + ch*8, true);
        }
        #pragma unroll
        for (int p = 0; p < 2; p++){
            int j = tid + p*256;
            int row = j >> 2, ch = j & 3;
            bool ok = !BOUND || (bn + row) < N;
            const __half* src = ok ? (Bt + (size_t)(bn+row)*K + k0 + ch*8) : Bt;
            cp16(sB + buf*G16_BUFB + row*(ROWP*2) + ch*16, src, ok);
        }
    };

    float acc[4][4][4];
    #pragma unroll
    for (int i=0;i<4;i++)
        #pragma unroll
        for (int j=0;j<4;j++)
            #pragma unroll
            for (int r=0;r<4;r++) acc[i][j][r]=0.f;

    ldgsts(0, 0); CP_COMMIT();
    ldgsts(1, 1); CP_COMMIT();

    // per-lane ldmatrix address components (bytes within a stage)
    const unsigned a_off = (wm*64 + (lane&15))*(ROWP*2) + ((lane>>4)<<4);
    const unsigned b_off = (wn*32 + ((lane>>4)<<3) + (lane&7))*(ROWP*2)
                         + (((lane>>3)&1)<<4);

    for (int t = 0; t < T; t++){
        const int buf = t % 3;
        if (t == T-1) { CP_WAIT0(); } else { CP_WAIT1(); }
        __syncthreads();
        if (t + 2 < T){ ldgsts(t+2, (t+2)%3); CP_COMMIT(); }

        const unsigned a_base = sA + buf*G16_BUFB + a_off;
        const unsigned b_base = sB + buf*G16_BUFB + b_off;

        #pragma unroll
        for (int ks = 0; ks < 2; ks++){
            const int kk = ks*16;
            unsigned af[4][4];
            #pragma unroll
            for (int mt = 0; mt < 4; mt++)
                ldsm4(af[mt], a_base + mt*16*(ROWP*2) + kk*2);
            unsigned bf[2][4];   // [pair][4 regs]: regs 0,1 = frag nt, 2,3 = nt+1
            #pragma unroll
            for (int pr = 0; pr < 2; pr++)
                ldsm4(bf[pr], b_base + pr*16*(ROWP*2) + kk*2);
            #pragma unroll
            for (int mt = 0; mt < 4; mt++){
                mma_f16(acc[mt][0], af[mt], &bf[0][0]);
                mma_f16(acc[mt][1], af[mt], &bf[0][2]);
                mma_f16(acc[mt][2], af[mt], &bf[1][0]);
                mma_f16(acc[mt][3], af[mt], &bf[1][2]);
            }
        }
    }

    __syncthreads();   // all warps done with last buffers before epilogue reuse-free exit

    #pragma unroll
    for (int mt = 0; mt < 4; mt++){
        #pragma unroll
        for (int nt = 0; nt < 4; nt++){
            int col  = bn + wn*32 + nt*8 + 2*(lane&3);
            int row0 = bm + wm*64 + mt*16 + (lane>>2);
            float b0 = 0.f, b1 = 0.f;
            if (EPI >= 2){ b0 = bias[col]; b1 = bias[col+1]; }
            #pragma unroll
            for (int half = 0; half < 2; half++){
                int row = row0 + half*8;
                float v0 = acc[mt][nt][half*2+0] + b0;
                float v1 = acc[mt][nt][half*2+1] + b1;
                if (EPI == 2){
                    const float* rr = resid + (size_t)row*N + col;
                    v0 += rr[0]; v1 += rr[1];
                }
                if (EPI == 3){ v0 = gelu_exact(v0); v1 = gelu_exact(v1); }
                if (EPI == 3 || EPI == 4){
                    __half2 hv = __floats2half2_rn(v0, v1);
                    *(__half2*)((__half*)Cv + (size_t)row*N + col) = hv;
                } else if (EPI == 0){
                    float* C = (float*)Cv;
                    if (!BOUND || col   < N) C[(size_t)row*N + col]     = v0;
                    if (!BOUND || col+1 < N) C[(size_t)row*N + col + 1] = v1;
                } else {
                    *(float2*)((float*)Cv + (size_t)row*N + col) = make_float2(v0, v1);
                }
            }
        }
    }
}

// =====================================================================
// tensor-core flash attention (R9-proven, unchanged)
// =====================================================================
#define FSTR 72
#define FTILEB (64*FSTR*2)

__global__ __launch_bounds__(128, 3) void flash_attn16(
    const __half* __restrict__ qkv, __half* __restrict__ y)
{
    __shared__ __half sK[2][64*FSTR];
    __shared__ __half sV[2][64*FSTR];

    const int qt = gridDim.x - 1 - blockIdx.x;
    const int h  = blockIdx.y;
    const int b  = blockIdx.z;
    const int tid  = threadIdx.x;
    const int lane = tid & 31;
    const int w    = tid >> 5;
    const int q0   = qt * 64;

    const unsigned skb = (unsigned)__cvta_generic_to_shared(&sK[0][0]);
    const unsigned svb = (unsigned)__cvta_generic_to_shared(&sV[0][0]);

    {
        int row = tid >> 1, hf = tid & 1;
        const __half* src = qkv + (size_t)(b*TMAXS + q0 + row)*(3*DMODEL) + h*HD + hf*32;
        unsigned dst = skb + row*144 + hf*64;
        #pragma unroll
        for (int c = 0; c < 4; c++) cp16(dst + c*16, src + c*8, true);
        CP_COMMIT(); CP_WAIT0();
    }
    __syncthreads();
    unsigned qa[4][4];
    #pragma unroll
    for (int ks = 0; ks < 4; ks++)
        ldsm4(qa[ks], skb + (16*w + (lane&15))*144 + ((lane>>4)<<4) + ks*32);
    __syncthreads();

    auto stage = [&](int kt, int buf){
        int row = tid >> 1, hf = tid & 1;
        size_t roff = (size_t)(b*TMAXS + kt*64 + row)*(3*DMODEL) + h*HD;
        const __half* sk = qkv + roff + DMODEL   + hf*32;
        const __half* sv = qkv + roff + 2*DMODEL + hf*32;
        unsigned dk = skb + buf*FTILEB + row*144 + hf*64;
        unsigned dv = svb + buf*FTILEB + row*144 + hf*64;
        #pragma unroll
        for (int c = 0; c < 4; c++){
            cp16(dk + c*16, sk + c*8, true);
            cp16(dv + c*16, sv + c*8, true);
        }
    };

    float o[8][4];
    #pragma unroll
    for (int i=0;i<8;i++){ o[i][0]=0.f; o[i][1]=0.f; o[i][2]=0.f; o[i][3]=0.f; }
    float m0 = -INFINITY, m1 = -INFINITY, l0 = 0.f, l1 = 0.f;
    const int r0g = q0 + 16*w + (lane>>2);
    const int r1g = r0g + 8;

    stage(0, 0); CP_COMMIT();

    for (int kt = 0; kt <= qt; kt++){
        const int buf = kt & 1;
        if (kt < qt){ stage(kt+1, buf^1); CP_COMMIT(); CP_WAIT1(); }
        else        { CP_WAIT0(); }
        __syncthreads();

        float s[8][4];
        #pragma unroll
        for (int i=0;i<8;i++){ s[i][0]=0.f; s[i][1]=0.f; s[i][2]=0.f; s[i][3]=0.f; }
        #pragma unroll
        for (int ks = 0; ks < 4; ks++){
            #pragma unroll
            for (int p = 0; p < 4; p++){
                unsigned bfr[4];
                ldsm4(bfr, skb + buf*FTILEB
                      + ((lane&7) + ((lane>>4)&1)*8 + 16*p)*144
                      + ((lane>>3)&1)*16 + ks*32);
                mma_f16(s[2*p],   qa[ks], &bfr[0]);
                mma_f16(s[2*p+1], qa[ks], &bfr[2]);
            }
        }

        const bool diag = (kt == qt);
        float mx0 = -INFINITY, mx1 = -INFINITY;
        #pragma unroll
        for (int nt = 0; nt < 8; nt++){
            #pragma unroll
            for (int j = 0; j < 2; j++){
                int kg = kt*64 + 8*nt + 2*(lane&3) + j;
                float v0 = s[nt][j]   * 0.125f;
                float v1 = s[nt][2+j] * 0.125f;
                if (diag && kg > r0g) v0 = -INFINITY;
                if (diag && kg > r1g) v1 = -INFINITY;
                s[nt][j]   = v0;
                s[nt][2+j] = v1;
                mx0 = fmaxf(mx0, v0);
                mx1 = fmaxf(mx1, v1);
            }
        }
        mx0 = fmaxf(mx0, __shfl_xor_sync(0xffffffffu, mx0, 1));
        mx0 = fmaxf(mx0, __shfl_xor_sync(0xffffffffu, mx0, 2));
        mx1 = fmaxf(mx1, __shfl_xor_sync(0xffffffffu, mx1, 1));
        mx1 = fmaxf(mx1, __shfl_xor_sync(0xffffffffu, mx1, 2));
        const float mn0 = fmaxf(m0, mx0), mn1 = fmaxf(m1, mx1);
        const float e0 = __expf(m0 - mn0), e1 = __expf(m1 - mn1);
        m0 = mn0; m1 = mn1;
        float ls0 = 0.f, ls1 = 0.f;
        #pragma unroll
        for (int nt = 0; nt < 8; nt++){
            #pragma unroll
            for (int j = 0; j < 2; j++){
                float p0 = __expf(s[nt][j]   - mn0);
                float p1 = __expf(s[nt][2+j] - mn1);
                s[nt][j]   = p0;
                s[nt][2+j] = p1;
                ls0 += p0; ls1 += p1;
            }
        }
        ls0 += __shfl_xor_sync(0xffffffffu, ls0, 1);
        ls0 += __shfl_xor_sync(0xffffffffu, ls0, 2);
        ls1 += __shfl_xor_sync(0xffffffffu, ls1, 1);
        ls1 += __shfl_xor_sync(0xffffffffu, ls1, 2);
        l0 = l0*e0 + ls0;
        l1 = l1*e1 + ls1;
        #pragma unroll
        for (int dt = 0; dt < 8; dt++){
            o[dt][0] *= e0; o[dt][1] *= e0;
            o[dt][2] *= e1; o[dt][3] *= e1;
        }

        unsigned pa[4][4];
        #pragma unroll
        for (int ks = 0; ks < 4; ks++){
            pa[ks][0] = packh2(s[2*ks][0],   s[2*ks][1]);
            pa[ks][1] = packh2(s[2*ks][2],   s[2*ks][3]);
            pa[ks][2] = packh2(s[2*ks+1][0], s[2*ks+1][1]);
            pa[ks][3] = packh2(s[2*ks+1][2], s[2*ks+1][3]);
        }

        #pragma unroll
        for (int ks = 0; ks < 4; ks++){
            #pragma unroll
            for (int p = 0; p < 4; p++){
                unsigned bfr[4];
                ldsm4t(bfr, svb + buf*FTILEB
                       + (16*ks + (lane&7) + ((lane>>3)&1)*8)*144
                       + (16*p + ((lane>>4)&1)*8)*2);
                mma_f16(o[2*p],   pa[ks], &bfr[0]);
                mma_f16(o[2*p+1], pa[ks], &bfr[2]);
            }
        }
        __syncthreads();
    }

    const float i0 = 1.0f / l0, i1 = 1.0f / l1;
    __half* y0 = y + (size_t)(b*TMAXS + r0g)*DMODEL + h*HD + 2*(lane&3);
    __half* y1 = y + (size_t)(b*TMAXS + r1g)*DMODEL + h*HD + 2*(lane&3);
    #pragma unroll
    for (int dt = 0; dt < 8; dt++){
        *(__half2*)(y0 + 8*dt) = __floats2half2_rn(o[dt][0]*i0, o[dt][1]*i0);
        *(__half2*)(y1 + 8*dt) = __floats2half2_rn(o[dt][2]*i1, o[dt][3]*i1);
    }
}

// ---------------- host orchestration ----------------
extern "C" void kernel_launch(void* const* d_in, const int* in_sizes, int n_in,
                              void* d_out, int out_size)
{
    const int*   ids    = (const int*)  d_in[0];
    const float* wte    = (const float*)d_in[1];
    const float* wpe    = (const float*)d_in[2];
    const float* ln1_g  = (const float*)d_in[3];
    const float* ln1_b  = (const float*)d_in[4];
    const float* attn_w = (const float*)d_in[5];
    const float* attn_b = (const float*)d_in[6];
    const float* proj_w = (const float*)d_in[7];
    const float* proj_b = (const float*)d_in[8];
    const float* ln2_g  = (const float*)d_in[9];
    const float* ln2_b  = (const float*)d_in[10];
    const float* fc_w   = (const float*)d_in[11];
    const float* fc_b   = (const float*)d_in[12];
    const float* fc2_w  = (const float*)d_in[13];
    const float* fc2_b  = (const float*)d_in[14];
    const float* lnf_g  = (const float*)d_in[15];
    const float* lnf_b  = (const float*)d_in[16];
    float* out = (float*)d_out;

    float  *x;
    __half *qkv16, *h16, *y16, *fc16, *wq16, *wp16, *wf16, *wf216, *wte16;
    cudaGetSymbolAddress((void**)&x,     g_x);
    cudaGetSymbolAddress((void**)&qkv16, g_qkv16);
    cudaGetSymbolAddress((void**)&h16,   g_h16);
    cudaGetSymbolAddress((void**)&y16,   g_y16);
    cudaGetSymbolAddress((void**)&fc16,  g_fc16);
    cudaGetSymbolAddress((void**)&wq16,  g_wqkv16);
    cudaGetSymbolAddress((void**)&wp16,  g_wproj16);
    cudaGetSymbolAddress((void**)&wf16,  g_wfc16);
    cudaGetSymbolAddress((void**)&wf216, g_wfc216);
    cudaGetSymbolAddress((void**)&wte16, g_wte16);

    cudaFuncSetAttribute(gemm16<0,true >, cudaFuncAttributeMaxDynamicSharedMemorySize, G16_SMEM);
    cudaFuncSetAttribute(gemm16<2,false>, cudaFuncAttributeMaxDynamicSharedMemorySize, G16_SMEM);
    cudaFuncSetAttribute(gemm16<3,false>, cudaFuncAttributeMaxDynamicSharedMemorySize, G16_SMEM);
    cudaFuncSetAttribute(gemm16<4,false>, cudaFuncAttributeMaxDynamicSharedMemorySize, G16_SMEM);

    // ---- weight prep ----
    {
        dim3 blk(32, 8);
        transpose_to_half<<<dim3(3*DMODEL/32, DMODEL/32, LAYERS), blk>>>(attn_w, wq16, DMODEL, 3*DMODEL);
        transpose_to_half<<<dim3(DMODEL/32,   DMODEL/32, LAYERS), blk>>>(proj_w, wp16, DMODEL, DMODEL);
        transpose_to_half<<<dim3(4*DMODEL/32, DMODEL/32, LAYERS), blk>>>(fc_w,   wf16, DMODEL, 4*DMODEL);
        transpose_to_half<<<dim3(DMODEL/32, 4*DMODEL/32, LAYERS), blk>>>(fc2_w,  wf216, 4*DMODEL, DMODEL);
        size_t n4 = (size_t)VOCAB*DMODEL/4;
        convert_to_half<<<(unsigned)((n4 + 255)/256), 256>>>(wte, wte16, n4);
    }

    embed_kernel<<<(MROWS*DMODEL + 255)/256, 256>>>(ids, wte, wpe, x);

    for (int l = 0; l < LAYERS; l++){
        layernorm_kernel<<<MROWS, 256>>>(x, h16, ln1_g + l*DMODEL, ln1_b + l*DMODEL);

        gemm16<4,false><<<dim3(3*DMODEL/128, MROWS/128), 256, G16_SMEM>>>(
            h16, wq16 + (size_t)l*3*DMODEL*DMODEL, attn_b + (size_t)l*3*DMODEL,
            nullptr, qkv16, MROWS, 3*DMODEL, DMODEL);

        flash_attn16<<<dim3(TMAXS/64, NHEAD, BATCH), 128>>>(qkv16, y16);

        gemm16<2,false><<<dim3(DMODEL/128, MROWS/128), 256, G16_SMEM>>>(
            y16, wp16 + (size_t)l*DMODEL*DMODEL, proj_b + (size_t)l*DMODEL,
            x, x, MROWS, DMODEL, DMODEL);

        layernorm_kernel<<<MROWS, 256>>>(x, h16, ln2_g + l*DMODEL, ln2_b + l*DMODEL);

        gemm16<3,false><<<dim3(4*DMODEL/128, MROWS/128), 256, G16_SMEM>>>(
            h16, wf16 + (size_t)l*4*DMODEL*DMODEL, fc_b + (size_t)l*4*DMODEL,
            nullptr, fc16, MROWS, 4*DMODEL, DMODEL);

        gemm16<2,false><<<dim3(DMODEL/128, MROWS/128), 256, G16_SMEM>>>(
            fc16, wf216 + (size_t)l*DMODEL*4*DMODEL, fc2_b + (size_t)l*DMODEL,
            x, x, MROWS, DMODEL, 4*DMODEL);
    }

    layernorm_kernel<<<MROWS, 256>>>(x, h16, lnf_g, lnf_b);

    gemm16<0,true><<<dim3((VOCAB + 127)/128, MROWS/128), 256, G16_SMEM>>>(
        h16, wte16, nullptr, nullptr, out, MROWS, VOCAB, DMODEL);
}